// round 13
// baseline (speedup 1.0000x reference)
#include <cuda_runtime.h>
#include <cuda_bf16.h>
#include <cstdint>

#define B_    32
#define T_    2000
#define F_    80
#define H_    256
#define S_    100
#define D_    512        // 2*H
#define M_    (B_*T_)    // 64000
#define N2_   2048       // 2 dirs * 4H

typedef unsigned long long ull;

// ------------------- packed f32x2 helpers (FFMA2) -------------------
__device__ __forceinline__ ull pack2(float x, float y) {
    ull r; asm("mov.b64 %0, {%1, %2};" : "=l"(r) : "f"(x), "f"(y)); return r;
}
__device__ __forceinline__ float2 unpack2(ull v) {
    float2 r; asm("mov.b64 {%0, %1}, %2;" : "=f"(r.x), "=f"(r.y) : "l"(v)); return r;
}
__device__ __forceinline__ void fma2(ull& d, ull a, ull b) {
    asm("fma.rn.f32x2 %0, %1, %2, %0;" : "+l"(d) : "l"(a), "l"(b));
}
__device__ __forceinline__ float rcpa(float x) {
    float r; asm("rcp.approx.f32 %0, %1;" : "=f"(r) : "f"(x)); return r;
}
__device__ __forceinline__ float sig_fast(float x) {
    return rcpa(1.f + __expf(-x));
}
__device__ __forceinline__ float tanh_fast(float x) {
    float e = __expf(2.f * x);
    return 1.f - 2.f * rcpa(e + 1.f);
}
__device__ __forceinline__ unsigned ld_acq(const unsigned* p) {
    unsigned v;
    asm volatile("ld.acquire.gpu.global.u32 %0, [%1];" : "=r"(v) : "l"(p) : "memory");
    return v;
}
__device__ __forceinline__ void red_rel(unsigned* p) {
    asm volatile("red.release.gpu.global.add.u32 [%0], 1;" :: "l"(p) : "memory");
}
__device__ __forceinline__ void cp16(uint32_t dst, const void* src) {
    asm volatile("cp.async.cg.shared.global [%0], [%1], 16;" :: "r"(dst), "l"(src));
}

// ------------------- scratch (static __device__, no allocs) -------------------
__device__ float g_x1 [(size_t)M_*256];          // conv1 out
__device__ float g_x2 [(size_t)M_*256];          // conv2 out
__device__ float g_gproj[(size_t)M_*N2_];        // input projections (reused L0/L1)
__device__ float g_gp2  [(size_t)2*T_*1024*B_];  // permuted [dir][s][n][b]
__device__ float g_houtp[(size_t)2*T_*H_*B_];    // scan out [dir][s][u][b]
__device__ float g_hout0[(size_t)M_*D_];         // layer0 bilstm out [b][t][d]
__device__ float g_hout1[(size_t)M_*D_];         // layer1 bilstm out
__device__ float g_w1t [256*256];                // padded K 240->256 (zero rows)
__device__ float g_w2t [768*256];
__device__ float g_wih0t[(size_t)256*N2_];
__device__ float g_wih1t[(size_t)512*N2_];
__device__ float g_wseg1t[D_*D_];
__device__ float g_wutt1t[D_*D_];
__device__ float g_pooled[B_*D_];
__device__ float g_hstate[2][2][2][H_*B_];       // [layer][buf][dir][k*32+b]
__device__ unsigned g_cnt[2][2][512];            // [layer][dir][8 counters x 64 pad]

// ------------------- fused prep: all transposes + state zeroing -------------
__global__ void k_prep(const float* __restrict__ c1w, const float* __restrict__ c2w,
                       const float* __restrict__ wih0, const float* __restrict__ wih1,
                       const float* __restrict__ segw1, const float* __restrict__ uttw1)
{
    int stride = gridDim.x * blockDim.x;
    int tid = blockIdx.x * blockDim.x + threadIdx.x;

    // conv1 w: [Co][Ci][3] -> [3*Ci][Co], rows 240..255 zero (K padded to 256)
    for (int i = tid; i < 256 * 256; i += stride) {
        int row = i >> 8, co = i & 255;
        float v = 0.f;
        if (row < 240) {
            int k = row / 80, ci = row % 80;
            v = c1w[co * 240 + ci * 3 + k];
        }
        g_w1t[row * 256 + co] = v;
    }
    for (int i = tid; i < 256 * 256 * 3; i += stride) {      // conv2 w
        int k = i % 3, ci = (i / 3) % 256, co = i / 768;
        g_w2t[(k * 256 + ci) * 256 + co] = c2w[i];
    }
    for (int i = tid; i < 2048 * 256; i += stride) {
        int k = i % 256, dr = i / 256;
        g_wih0t[(size_t)k * 2048 + dr] = wih0[i];
    }
    for (int i = tid; i < 2048 * 512; i += stride) {
        int k = i % 512, dr = i / 512;
        g_wih1t[(size_t)k * 2048 + dr] = wih1[i];
    }
    for (int i = tid; i < D_ * D_; i += stride) {
        int d = i / D_, k = i % D_;
        g_wseg1t[k * D_ + d] = segw1[i];
        g_wutt1t[k * D_ + d] = uttw1[i];
    }
    {
        float* p = &g_hstate[0][0][0][0];
        for (int i = tid; i < 2 * 2 * 2 * H_ * B_; i += stride) p[i] = 0.f;
        unsigned* c = &g_cnt[0][0][0];
        for (int i = tid; i < 2 * 2 * 512; i += stride) c[i] = 0u;
    }
}

// ---- permute gproj -> gp2[dir][s][n][b], reversal folded in ----
__global__ void __launch_bounds__(256)
k_permute(const float* __restrict__ gproj, float* __restrict__ gp2,
          const int* __restrict__ len)
{
    __shared__ float tile[32][65];
    __shared__ int Ls[32];
    int s = blockIdx.x, nc = blockIdx.y, dir = blockIdx.z;
    int tid = threadIdx.x;
    if (tid < 32) Ls[tid] = len[tid];
    __syncthreads();

    int b  = tid >> 3;
    int ng = (tid & 7) * 8;
    int L  = Ls[b];
    int t  = dir ? (L - 1 - s) : s;
    bool ok = (s < L);
    int n0 = nc * 64;
    const float* src = gproj + ((size_t)b * T_ + (ok ? t : 0)) * N2_ + dir * 1024 + n0 + ng;
    float4 v0 = make_float4(0.f, 0.f, 0.f, 0.f), v1 = v0;
    if (ok) { v0 = *(const float4*)src; v1 = *(const float4*)(src + 4); }
    tile[b][ng + 0] = v0.x; tile[b][ng + 1] = v0.y;
    tile[b][ng + 2] = v0.z; tile[b][ng + 3] = v0.w;
    tile[b][ng + 4] = v1.x; tile[b][ng + 5] = v1.y;
    tile[b][ng + 6] = v1.z; tile[b][ng + 7] = v1.w;
    __syncthreads();

    float* dst = gp2 + (((size_t)dir * T_ + s) * 1024 + n0) * 32;
    int bb = tid & 31;
#pragma unroll
    for (int i = 0; i < 8; i++) {
        int nl = (tid >> 5) + i * 8;
        dst[(size_t)nl * 32 + bb] = tile[bb][nl];
    }
}

// ---- unpermute houtp[dir][s][u][b] -> hout[b][t][dir*H+u] ----
__global__ void __launch_bounds__(256)
k_unpermute(const float* __restrict__ houtp, float* __restrict__ hout,
            const int* __restrict__ len)
{
    __shared__ float tile[64][33];
    __shared__ int Ls[32];
    int s = blockIdx.x, uc = blockIdx.y, dir = blockIdx.z;
    int tid = threadIdx.x;
    if (tid < 32) Ls[tid] = len[tid];
    __syncthreads();

    const float* src = houtp + (((size_t)dir * T_ + s) * H_ + uc * 64) * 32;
    int ur = tid >> 5, b = tid & 31;
#pragma unroll
    for (int j = 0; j < 8; j++) {
        int u = ur * 8 + j;
        tile[u][b] = src[(size_t)u * 32 + b];
    }
    __syncthreads();

    int b2 = tid >> 3, ug = tid & 7;
    int L = Ls[b2];
    int t = (s < L) ? (dir ? (L - 1 - s) : s) : s;
    float v[8];
#pragma unroll
    for (int j = 0; j < 8; j++) v[j] = tile[ug * 8 + j][b2];
    float* dst = hout + ((size_t)b2 * T_ + t) * D_ + dir * H_ + uc * 64 + ug * 8;
    *(float4*)dst       = make_float4(v[0], v[1], v[2], v[3]);
    *(float4*)(dst + 4) = make_float4(v[4], v[5], v[6], v[7]);
}

// ---- tiled SGEMM (f32x2), GBK=32, cp.async double-buffer (CI==0 path) ----
#define GBM 128
#define GBN 128
#define GBK 32
#define GEMM_SMEM (4 * GBK * 132 * 4)    // As[2]+Bs[2]

template <int CI>
__global__ void __launch_bounds__(256, 2)
k_gemm(const float* __restrict__ A, const float* __restrict__ Bm,
       const float* __restrict__ bias, float* __restrict__ C,
       int M, int N, int K, int relu)
{
    extern __shared__ float gsm[];
    float (*As)[GBK][132] = (float(*)[GBK][132])gsm;
    float (*Bs)[GBK][132] = (float(*)[GBK][132])(gsm + 2 * GBK * 132);

    int bm = blockIdx.y * GBM;
    int bn = blockIdx.x * GBN;
    int tid = threadIdx.x;
    int tr = tid >> 4;
    int tc = tid & 15;

    ull acc[4][8];
#pragma unroll
    for (int i = 0; i < 4; i++)
#pragma unroll
        for (int j = 0; j < 8; j++) acc[i][j] = 0ull;

    if (CI == 0) {
        // ---- pipelined path: B via cp.async, A via register prefetch ----
        int ntiles = K / GBK;
        float4 areg[4];

#pragma unroll
        for (int i = 0; i < 4; i++) {
            int idx = tid + i * 256;
            int kr = idx >> 5, n4 = (idx & 31) * 4;
            cp16((uint32_t)__cvta_generic_to_shared(&Bs[0][kr][n4]),
                 &Bm[(size_t)kr * N + bn + n4]);
        }
        asm volatile("cp.async.commit_group;");
#pragma unroll
        for (int i = 0; i < 4; i++) {
            int idx = tid + i * 256;
            int row = idx >> 3, c4 = (idx & 7) * 4;
            areg[i] = *(const float4*)&A[(size_t)(bm + row) * K + c4];
        }

        for (int it = 0; it < ntiles; it++) {
            int buf = it & 1;
#pragma unroll
            for (int i = 0; i < 4; i++) {
                int idx = tid + i * 256;
                int row = idx >> 3, c4 = (idx & 7) * 4;
                As[buf][c4 + 0][row] = areg[i].x;
                As[buf][c4 + 1][row] = areg[i].y;
                As[buf][c4 + 2][row] = areg[i].z;
                As[buf][c4 + 3][row] = areg[i].w;
            }
            if (it + 1 < ntiles) {
                int k1 = (it + 1) * GBK;
#pragma unroll
                for (int i = 0; i < 4; i++) {
                    int idx = tid + i * 256;
                    int kr = idx >> 5, n4 = (idx & 31) * 4;
                    cp16((uint32_t)__cvta_generic_to_shared(&Bs[buf ^ 1][kr][n4]),
                         &Bm[(size_t)(k1 + kr) * N + bn + n4]);
                }
                asm volatile("cp.async.commit_group;");
#pragma unroll
                for (int i = 0; i < 4; i++) {
                    int idx = tid + i * 256;
                    int row = idx >> 3, c4 = (idx & 7) * 4;
                    areg[i] = *(const float4*)&A[(size_t)(bm + row) * K + k1 + c4];
                }
                asm volatile("cp.async.wait_group 1;");
            } else {
                asm volatile("cp.async.wait_group 0;");
            }
            __syncthreads();
#pragma unroll 16
            for (int k = 0; k < GBK; k++) {
                ulonglong2 a0 = *(const ulonglong2*)&As[buf][k][tr * 8];
                ulonglong2 a1 = *(const ulonglong2*)&As[buf][k][tr * 8 + 4];
                float4 b0 = *(const float4*)&Bs[buf][k][tc * 4];
                float4 b1 = *(const float4*)&Bs[buf][k][tc * 4 + 64];
                ull ar0 = a0.x, ar1 = a0.y, ar2 = a1.x, ar3 = a1.y;
                ull bd0 = pack2(b0.x, b0.x), bd1 = pack2(b0.y, b0.y);
                ull bd2 = pack2(b0.z, b0.z), bd3 = pack2(b0.w, b0.w);
                ull bd4 = pack2(b1.x, b1.x), bd5 = pack2(b1.y, b1.y);
                ull bd6 = pack2(b1.z, b1.z), bd7 = pack2(b1.w, b1.w);
                fma2(acc[0][0], ar0, bd0); fma2(acc[0][1], ar0, bd1);
                fma2(acc[0][2], ar0, bd2); fma2(acc[0][3], ar0, bd3);
                fma2(acc[0][4], ar0, bd4); fma2(acc[0][5], ar0, bd5);
                fma2(acc[0][6], ar0, bd6); fma2(acc[0][7], ar0, bd7);
                fma2(acc[1][0], ar1, bd0); fma2(acc[1][1], ar1, bd1);
                fma2(acc[1][2], ar1, bd2); fma2(acc[1][3], ar1, bd3);
                fma2(acc[1][4], ar1, bd4); fma2(acc[1][5], ar1, bd5);
                fma2(acc[1][6], ar1, bd6); fma2(acc[1][7], ar1, bd7);
                fma2(acc[2][0], ar2, bd0); fma2(acc[2][1], ar2, bd1);
                fma2(acc[2][2], ar2, bd2); fma2(acc[2][3], ar2, bd3);
                fma2(acc[2][4], ar2, bd4); fma2(acc[2][5], ar2, bd5);
                fma2(acc[2][6], ar2, bd6); fma2(acc[2][7], ar2, bd7);
                fma2(acc[3][0], ar3, bd0); fma2(acc[3][1], ar3, bd1);
                fma2(acc[3][2], ar3, bd2); fma2(acc[3][3], ar3, bd3);
                fma2(acc[3][4], ar3, bd4); fma2(acc[3][5], ar3, bd5);
                fma2(acc[3][6], ar3, bd6); fma2(acc[3][7], ar3, bd7);
            }
            __syncthreads();
        }
    } else {
        // ---- im2col path (convs): synchronous single-buffer ----
        int Kr = (K + GBK - 1) & ~(GBK - 1);
        for (int k0 = 0; k0 < Kr; k0 += GBK) {
#pragma unroll
            for (int i = 0; i < 4; i++) {
                int idx = tid + i * 256;
                int row = idx >> 3;
                int c4 = (idx & 7) * 4;
                int r = bm + row;
                int b = r / T_, t = r % T_;
                int kk = k0 + c4;
                int kt = kk / CI, ci = kk - kt * CI;
                int tt = t + kt - 1;
                float4 v = (kk < K && tt >= 0 && tt < T_)
                    ? *(const float4*)&A[((size_t)b * T_ + tt) * CI + ci]
                    : make_float4(0.f, 0.f, 0.f, 0.f);
                As[0][c4 + 0][row] = v.x;
                As[0][c4 + 1][row] = v.y;
                As[0][c4 + 2][row] = v.z;
                As[0][c4 + 3][row] = v.w;
            }
#pragma unroll
            for (int i = 0; i < 4; i++) {
                int idx = tid + i * 256;
                int kr = idx >> 5;
                int n4 = (idx & 31) * 4;
                *(float4*)&Bs[0][kr][n4] = *(const float4*)&Bm[(size_t)(k0 + kr) * N + bn + n4];
            }
            __syncthreads();
#pragma unroll 16
            for (int k = 0; k < GBK; k++) {
                ulonglong2 a0 = *(const ulonglong2*)&As[0][k][tr * 8];
                ulonglong2 a1 = *(const ulonglong2*)&As[0][k][tr * 8 + 4];
                float4 b0 = *(const float4*)&Bs[0][k][tc * 4];
                float4 b1 = *(const float4*)&Bs[0][k][tc * 4 + 64];
                ull ar0 = a0.x, ar1 = a0.y, ar2 = a1.x, ar3 = a1.y;
                ull bd0 = pack2(b0.x, b0.x), bd1 = pack2(b0.y, b0.y);
                ull bd2 = pack2(b0.z, b0.z), bd3 = pack2(b0.w, b0.w);
                ull bd4 = pack2(b1.x, b1.x), bd5 = pack2(b1.y, b1.y);
                ull bd6 = pack2(b1.z, b1.z), bd7 = pack2(b1.w, b1.w);
                fma2(acc[0][0], ar0, bd0); fma2(acc[0][1], ar0, bd1);
                fma2(acc[0][2], ar0, bd2); fma2(acc[0][3], ar0, bd3);
                fma2(acc[0][4], ar0, bd4); fma2(acc[0][5], ar0, bd5);
                fma2(acc[0][6], ar0, bd6); fma2(acc[0][7], ar0, bd7);
                fma2(acc[1][0], ar1, bd0); fma2(acc[1][1], ar1, bd1);
                fma2(acc[1][2], ar1, bd2); fma2(acc[1][3], ar1, bd3);
                fma2(acc[1][4], ar1, bd4); fma2(acc[1][5], ar1, bd5);
                fma2(acc[1][6], ar1, bd6); fma2(acc[1][7], ar1, bd7);
                fma2(acc[2][0], ar2, bd0); fma2(acc[2][1], ar2, bd1);
                fma2(acc[2][2], ar2, bd2); fma2(acc[2][3], ar2, bd3);
                fma2(acc[2][4], ar2, bd4); fma2(acc[2][5], ar2, bd5);
                fma2(acc[2][6], ar2, bd6); fma2(acc[2][7], ar2, bd7);
                fma2(acc[3][0], ar3, bd0); fma2(acc[3][1], ar3, bd1);
                fma2(acc[3][2], ar3, bd2); fma2(acc[3][3], ar3, bd3);
                fma2(acc[3][4], ar3, bd4); fma2(acc[3][5], ar3, bd5);
                fma2(acc[3][6], ar3, bd6); fma2(acc[3][7], ar3, bd7);
            }
            __syncthreads();
        }
    }

    float bb[8];
    if (bias) {
        float4 bv0 = *(const float4*)&bias[bn + tc * 4];
        float4 bv1 = *(const float4*)&bias[bn + tc * 4 + 64];
        bb[0] = bv0.x; bb[1] = bv0.y; bb[2] = bv0.z; bb[3] = bv0.w;
        bb[4] = bv1.x; bb[5] = bv1.y; bb[6] = bv1.z; bb[7] = bv1.w;
    } else {
#pragma unroll
        for (int c = 0; c < 8; c++) bb[c] = 0.f;
    }
#pragma unroll
    for (int rp = 0; rp < 4; rp++) {
        float o0[8], o1[8];
#pragma unroll
        for (int c = 0; c < 8; c++) {
            float2 u = unpack2(acc[rp][c]);
            o0[c] = u.x + bb[c];
            o1[c] = u.y + bb[c];
            if (relu) { o0[c] = fmaxf(o0[c], 0.f); o1[c] = fmaxf(o1[c], 0.f); }
        }
        int row0 = bm + tr * 8 + rp * 2;
        float* p0 = &C[(size_t)row0 * N + bn];
        float* p1 = p0 + N;
        *(float4*)(p0 + tc * 4)      = make_float4(o0[0], o0[1], o0[2], o0[3]);
        *(float4*)(p0 + tc * 4 + 64) = make_float4(o0[4], o0[5], o0[6], o0[7]);
        *(float4*)(p1 + tc * 4)      = make_float4(o1[0], o1[1], o1[2], o1[3]);
        *(float4*)(p1 + tc * 4 + 64) = make_float4(o1[4], o1[5], o1[6], o1[7]);
    }
}

// ------------------- persistent BiLSTM scan (one layer, both dirs) ----------
// 128 CTAs x 256 threads. Quarter-scoped data deps (R10), but arrivals split
// over 8 counters/dir (8 producers each) to halve the LTS same-address drain.
// Consumer group kq waits on counters 2kq and 2kq+1 (pollers: lanes 0 and 32).
#define SCAN_NCTA 128
#define SCAN_SMEM ((8192 + 8192 + 2048) * 4 + 128)

__global__ void __launch_bounds__(256, 1)
k_scan(const float* __restrict__ gp2, const float* __restrict__ whh,
       const int* __restrict__ lengths, float* __restrict__ houtp, int layer)
{
    extern __shared__ float sm[];
    ull*   w2  = (ull*)sm;                 // [256][16] dup'd weights (32 KB)
    float* h_s = sm + 8192;                // [256][32] h (k-major, 32 KB)
    float* g_p = sm + 16384;               // [4][16][32] partial gates (8 KB)
    int*   L_s = (int*)(sm + 18432);       // [32]

    const int bid = blockIdx.x;
    const int dir = bid >> 6;
    const int u0  = (bid & 63) * 4;
    const int tid = threadIdx.x;

    for (int i = tid; i < 4096; i += 256) {
        int k = i >> 4, r = i & 15;
        int q = r >> 2, j = r & 3;
        float w = whh[(size_t)dir * 262144 + (size_t)(q * 256 + u0 + j) * 256 + k];
        w2[(size_t)k * 16 + r] = pack2(w, w);
    }
    if (tid < 32) L_s[tid] = lengths[tid];
    __syncthreads();

    const int kq = tid >> 6;             // k-quarter this group consumes
    const int eown = (bid & 63) >> 3;    // arrival counter this CTA bumps (0..7)
    const int lt = tid & 63;
    const int rp = lt >> 3;              // row pair 0..7
    const int b4 = tid & 7;              // batch quad 0..7
    const int cu = (tid >> 5) & 3;       // unit 0..3 (gate phase, tid<128)
    const int cb = tid & 31;             // batch   (gate phase, tid<128)
    const bool gthr = tid < 128;
    const int Lcb = L_s[cb];
    float creg = 0.f;

    unsigned* arrive_cnt = &g_cnt[layer][dir][eown * 64];
    // group kq consumes h-quarter kq, produced by CTAs arriving on counters
    // 2kq and 2kq+1 (8 CTAs each); lanes 0 and 32 of the group poll one each.
    unsigned* poll_cnt = &g_cnt[layer][dir][(kq * 2 + ((lt >> 5) & 1)) * 64];
    const bool poller = (lt & 31) == 0;

    const float* gbase = gp2 + ((size_t)dir * T_ * 1024 + u0 + cu) * 32 + cb;
    float* hpo = houtp + ((size_t)dir * T_ * H_ + u0 + cu) * 32 + cb;

    for (int s = 0; s < T_; s++) {
        bool act = s < Lcb;

        // prefetch gates for this step (DRAM; consumed ~2k cyc later)
        float pi = 0.f, pf = 0.f, pg = 0.f, po = 0.f;
        if (gthr) {
            const float* gp = gbase + (size_t)s * 1024 * 32;
            pi = __ldcg(gp);
            pf = __ldcg(gp + 256 * 32);
            pg = __ldcg(gp + 512 * 32);
            po = __ldcg(gp + 768 * 32);
        }

        // wait for the 8+8 producers of OUR quarter (two pollers), then load
        if (poller && s > 0) {
            unsigned tgt = (unsigned)s * 8u;
            while (ld_acq(poll_cnt) < tgt) { }
        }
        asm volatile("bar.sync %0, 64;" :: "r"(1 + kq) : "memory");
        {
            const float* hsrc = g_hstate[layer][s & 1][dir] + kq * 2048;
            float*       hdst = h_s + kq * 2048;
#pragma unroll
            for (int i = 0; i < 8; i++) {
                int idx = (lt + i * 64) * 4;
                *(float4*)(hdst + idx) = __ldcg((const float4*)(hsrc + idx));
            }
        }
        asm volatile("bar.sync %0, 64;" :: "r"(1 + kq) : "memory");

        // dot: rows (2rp,2rp+1) x batches (4b4..+3) over k-quarter, all FFMA2
        ull a00 = 0ull, a01 = 0ull, a10 = 0ull, a11 = 0ull;
        const ull*   wp = w2 + (size_t)(kq * 64) * 16 + rp * 2;
        const float* hp = h_s + (kq * 64) * 32 + b4 * 4;
#pragma unroll 8
        for (int k = 0; k < 64; k++) {
            ulonglong2 w = *(const ulonglong2*)wp;
            ulonglong2 h = *(const ulonglong2*)hp;
            fma2(a00, w.x, h.x); fma2(a01, w.x, h.y);
            fma2(a10, w.y, h.x); fma2(a11, w.y, h.y);
            wp += 16; hp += 32;
        }
        {
            float* gp0 = g_p + kq * 512 + (rp * 2) * 32 + b4 * 4;
            float2 u;
            u = unpack2(a00); gp0[0] = u.x; gp0[1] = u.y;
            u = unpack2(a01); gp0[2] = u.x; gp0[3] = u.y;
            float* gp1 = gp0 + 32;
            u = unpack2(a10); gp1[0] = u.x; gp1[1] = u.y;
            u = unpack2(a11); gp1[2] = u.x; gp1[3] = u.y;
        }
        __syncthreads();

        // gates + state update; thread (unit cu, batch cb), tid<128
        float h = 0.f;
        if (gthr && act) {
            float gi = pi, gf = pf, gg = pg, go = po;
#pragma unroll
            for (int q = 0; q < 4; q++) {
                gi += g_p[q * 512 + (cu)      * 32 + cb];
                gf += g_p[q * 512 + (4 + cu)  * 32 + cb];
                gg += g_p[q * 512 + (8 + cu)  * 32 + cb];
                go += g_p[q * 512 + (12 + cu) * 32 + cb];
            }
            gi = sig_fast(gi);
            gf = sig_fast(gf);
            go = sig_fast(go);
            gg = tanh_fast(gg);
            creg = gf * creg + gi * gg;
            h = go * tanh_fast(creg);
            __stcg(&g_hstate[layer][(s & 1) ^ 1][dir][(u0 + cu) * 32 + cb], h);
        }
        if (gthr) __stcg(hpo + (size_t)s * H_ * 32, h);

        // publish arrival on this CTA's counter
        __syncthreads();
        if (tid == 0) red_rel(arrive_cnt);
    }
}

// ------------------- pooling + heads -------------------
__global__ void k_pool(const float* __restrict__ hout, const int* __restrict__ len,
                       float* __restrict__ pooled) {
    int b = blockIdx.x;
    int c = blockIdx.y * 128 + threadIdx.x;
    float s = 0.f;
    const float* p = hout + (size_t)b * T_ * D_ + c;
    for (int t = 0; t < T_; t++) s += p[(size_t)t * D_];
    int L = len[b];
    pooled[b * D_ + c] = s / (float)(L > 1 ? L : 1);
}

__global__ void k_utt(const float* __restrict__ pooled, const float* __restrict__ w1t,
                      const float* __restrict__ b1, const float* __restrict__ w2,
                      const float* __restrict__ b2, float* __restrict__ out) {
    int b = blockIdx.x, d = threadIdx.x;
    __shared__ float ps[D_];
    __shared__ float red[D_];
    ps[d] = pooled[b * D_ + d];
    __syncthreads();
    float acc = b1[d];
    for (int k = 0; k < D_; k++) acc = fmaf(ps[k], w1t[k * D_ + d], acc);
    red[d] = fmaxf(acc, 0.f) * w2[d];
    __syncthreads();
    for (int st = 256; st > 0; st >>= 1) {
        if (d < st) red[d] += red[d + st];
        __syncthreads();
    }
    if (d == 0) out[b] = red[0] + b2[0];
}

__global__ void k_seg(const float* __restrict__ hout, const int* __restrict__ segs,
                      const int* __restrict__ len, const int* __restrict__ seglen,
                      const float* __restrict__ w1t, const float* __restrict__ b1,
                      const float* __restrict__ w2, const float* __restrict__ b2,
                      float* __restrict__ out) {
    int si = blockIdx.x, b = blockIdx.y, d = threadIdx.x;
    __shared__ float mean_s[D_];
    __shared__ float red[D_];
    int L = len[b];
    int s0 = segs[(b * S_ + si) * 2 + 0];
    int e0 = segs[(b * S_ + si) * 2 + 1];
    int s = min(max(s0, 0), L);
    int e = max(s + 1, min(e0, L));
    float cnt = (float)(e - s);
    int ec = min(e, T_);
    float acc = 0.f;
    const float* p = hout + ((size_t)b * T_ + s) * D_ + d;
    for (int t = s; t < ec; t++, p += D_) acc += *p;
    mean_s[d] = acc / cnt;
    __syncthreads();
    float hv = b1[d];
    for (int k = 0; k < D_; k++) hv = fmaf(mean_s[k], w1t[k * D_ + d], hv);
    red[d] = fmaxf(hv, 0.f) * w2[d];
    __syncthreads();
    for (int st = 256; st > 0; st >>= 1) {
        if (d < st) red[d] += red[d + st];
        __syncthreads();
    }
    if (d == 0) {
        float sc = red[0] + b2[0];
        out[B_ + b * S_ + si] = (si < seglen[b]) ? sc : 0.f;
    }
}

// ------------------- driver -------------------
extern "C" void kernel_launch(void* const* d_in, const int* in_sizes, int n_in,
                              void* d_out, int out_size) {
    const float* features = (const float*)d_in[0];
    const int*   feat_len = (const int*)d_in[1];
    const int*   segs     = (const int*)d_in[2];
    const int*   seg_len  = (const int*)d_in[3];
    const float* conv1_w  = (const float*)d_in[4];
    const float* conv1_b  = (const float*)d_in[5];
    const float* conv2_w  = (const float*)d_in[6];
    const float* conv2_b  = (const float*)d_in[7];
    const float* wih0     = (const float*)d_in[8];
    const float* whh0     = (const float*)d_in[9];
    const float* bias0    = (const float*)d_in[10];
    const float* wih1     = (const float*)d_in[11];
    const float* whh1     = (const float*)d_in[12];
    const float* bias1    = (const float*)d_in[13];
    const float* seg_w1   = (const float*)d_in[14];
    const float* seg_b1   = (const float*)d_in[15];
    const float* seg_w2   = (const float*)d_in[16];
    const float* seg_b2   = (const float*)d_in[17];
    const float* utt_w1   = (const float*)d_in[18];
    const float* utt_b1   = (const float*)d_in[19];
    const float* utt_w2   = (const float*)d_in[20];
    const float* utt_b2   = (const float*)d_in[21];
    float* out = (float*)d_out;

    cudaFuncSetAttribute(k_scan, cudaFuncAttributeMaxDynamicSharedMemorySize, SCAN_SMEM);
    cudaFuncSetAttribute(k_gemm<0>,   cudaFuncAttributeMaxDynamicSharedMemorySize, GEMM_SMEM);
    cudaFuncSetAttribute(k_gemm<80>,  cudaFuncAttributeMaxDynamicSharedMemorySize, GEMM_SMEM);
    cudaFuncSetAttribute(k_gemm<256>, cudaFuncAttributeMaxDynamicSharedMemorySize, GEMM_SMEM);

    float *x1, *x2, *gproj, *gp2, *houtp, *hout0, *hout1, *w1t, *w2t,
          *wih0t, *wih1t, *wseg1t, *wutt1t, *pooled;
    cudaGetSymbolAddress((void**)&x1,     g_x1);
    cudaGetSymbolAddress((void**)&x2,     g_x2);
    cudaGetSymbolAddress((void**)&gproj,  g_gproj);
    cudaGetSymbolAddress((void**)&gp2,    g_gp2);
    cudaGetSymbolAddress((void**)&houtp,  g_houtp);
    cudaGetSymbolAddress((void**)&hout0,  g_hout0);
    cudaGetSymbolAddress((void**)&hout1,  g_hout1);
    cudaGetSymbolAddress((void**)&w1t,    g_w1t);
    cudaGetSymbolAddress((void**)&w2t,    g_w2t);
    cudaGetSymbolAddress((void**)&wih0t,  g_wih0t);
    cudaGetSymbolAddress((void**)&wih1t,  g_wih1t);
    cudaGetSymbolAddress((void**)&wseg1t, g_wseg1t);
    cudaGetSymbolAddress((void**)&wutt1t, g_wutt1t);
    cudaGetSymbolAddress((void**)&pooled, g_pooled);

    // 1: fused prep
    k_prep<<<2048, 256>>>(conv1_w, conv2_w, wih0, wih1, seg_w1, utt_w1);
    // 2: conv1 (im2col fused, K=240 padded weights)
    k_gemm<80><<<dim3(256/GBN, M_/GBM), 256, GEMM_SMEM>>>(features, w1t, conv1_b, x1, M_, 256, 240, 1);
    // 3: conv2 (im2col fused)
    k_gemm<256><<<dim3(256/GBN, M_/GBM), 256, GEMM_SMEM>>>(x1, w2t, conv2_b, x2, M_, 256, 768, 1);
    // 4: layer-0 input projection
    k_gemm<0><<<dim3(N2_/GBN, M_/GBM), 256, GEMM_SMEM>>>(x2, wih0t, bias0, gproj, M_, N2_, 256, 0);
    // 5: permute gproj (reversal folded in)
    k_permute<<<dim3(T_, 16, 2), 256>>>(gproj, gp2, feat_len);
    // 6: layer-0 scan
    k_scan<<<SCAN_NCTA, 256, SCAN_SMEM>>>(gp2, whh0, feat_len, houtp, 0);
    // 7: unpermute layer-0 output
    k_unpermute<<<dim3(T_, 4, 2), 256>>>(houtp, hout0, feat_len);
    // 8: layer-1 input projection
    k_gemm<0><<<dim3(N2_/GBN, M_/GBM), 256, GEMM_SMEM>>>(hout0, wih1t, bias1, gproj, M_, N2_, 512, 0);
    // 9: permute
    k_permute<<<dim3(T_, 16, 2), 256>>>(gproj, gp2, feat_len);
    // 10: layer-1 scan
    k_scan<<<SCAN_NCTA, 256, SCAN_SMEM>>>(gp2, whh1, feat_len, houtp, 1);
    // 11: unpermute layer-1 output
    k_unpermute<<<dim3(T_, 4, 2), 256>>>(houtp, hout1, feat_len);

    // pooling + heads
    k_pool<<<dim3(B_, 4), 128>>>(hout1, feat_len, pooled);
    k_utt<<<B_, D_>>>(pooled, wutt1t, utt_b1, utt_w2, utt_b2, out);
    k_seg<<<dim3(S_, B_), D_>>>(hout1, segs, feat_len, seg_len,
                                wseg1t, seg_b1, seg_w2, seg_b2, out);
}

// round 14
// speedup vs baseline: 1.0190x; 1.0190x over previous
#include <cuda_runtime.h>
#include <cuda_bf16.h>
#include <cstdint>

#define B_    32
#define T_    2000
#define F_    80
#define H_    256
#define S_    100
#define D_    512        // 2*H
#define M_    (B_*T_)    // 64000
#define N2_   2048       // 2 dirs * 4H

typedef unsigned long long ull;

// ------------------- packed f32x2 helpers (FFMA2) -------------------
__device__ __forceinline__ ull pack2(float x, float y) {
    ull r; asm("mov.b64 %0, {%1, %2};" : "=l"(r) : "f"(x), "f"(y)); return r;
}
__device__ __forceinline__ float2 unpack2(ull v) {
    float2 r; asm("mov.b64 {%0, %1}, %2;" : "=f"(r.x), "=f"(r.y) : "l"(v)); return r;
}
__device__ __forceinline__ void fma2(ull& d, ull a, ull b) {
    asm("fma.rn.f32x2 %0, %1, %2, %0;" : "+l"(d) : "l"(a), "l"(b));
}
__device__ __forceinline__ float rcpa(float x) {
    float r; asm("rcp.approx.f32 %0, %1;" : "=f"(r) : "f"(x)); return r;
}
__device__ __forceinline__ float sig_fast(float x) {
    return rcpa(1.f + __expf(-x));
}
__device__ __forceinline__ float tanh_fast(float x) {
    float e = __expf(2.f * x);
    return 1.f - 2.f * rcpa(e + 1.f);
}
__device__ __forceinline__ unsigned ld_acq(const unsigned* p) {
    unsigned v;
    asm volatile("ld.acquire.gpu.global.u32 %0, [%1];" : "=r"(v) : "l"(p) : "memory");
    return v;
}
__device__ __forceinline__ void red_rel(unsigned* p) {
    asm volatile("red.release.gpu.global.add.u32 [%0], 1;" :: "l"(p) : "memory");
}
__device__ __forceinline__ void cp16(uint32_t dst, const void* src) {
    asm volatile("cp.async.cg.shared.global [%0], [%1], 16;" :: "r"(dst), "l"(src));
}

// ------------------- scratch (static __device__, no allocs) -------------------
__device__ float g_x1 [(size_t)M_*256];          // conv1 out
__device__ float g_x2 [(size_t)M_*256];          // conv2 out
__device__ float g_gproj[(size_t)M_*N2_];        // input projections (reused L0/L1)
__device__ float g_gp2  [(size_t)2*T_*1024*B_];  // permuted [dir][s][n][b]
__device__ float g_houtp[(size_t)2*T_*H_*B_];    // scan out [dir][s][u][b]
__device__ float g_hout0[(size_t)M_*D_];         // layer0 bilstm out [b][t][d]
__device__ float g_hout1[(size_t)M_*D_];         // layer1 bilstm out
__device__ float g_w1t [256*256];                // padded K 240->256 (zero rows)
__device__ float g_w2t [768*256];
__device__ float g_wih0t[(size_t)256*N2_];
__device__ float g_wih1t[(size_t)512*N2_];
__device__ float g_wseg1t[D_*D_];
__device__ float g_wutt1t[D_*D_];
__device__ float g_pooled[B_*D_];
__device__ float g_hstate[2][2][2][H_*B_];       // [layer][buf][dir][k*32+b]
__device__ unsigned g_cnt[2][2][256];            // [layer][dir][4 quarter counters x 64 pad]
__device__ int g_maxL;

// ------------------- fused prep: all transposes + state zeroing -------------
__global__ void k_prep(const float* __restrict__ c1w, const float* __restrict__ c2w,
                       const float* __restrict__ wih0, const float* __restrict__ wih1,
                       const float* __restrict__ segw1, const float* __restrict__ uttw1,
                       const int* __restrict__ len)
{
    int stride = gridDim.x * blockDim.x;
    int tid = blockIdx.x * blockDim.x + threadIdx.x;

    if (tid == 0) {
        int m = 1;
        for (int b = 0; b < B_; b++) m = max(m, len[b]);
        g_maxL = m;
    }

    // conv1 w: [Co][Ci][3] -> [3*Ci][Co], rows 240..255 zero (K padded to 256)
    for (int i = tid; i < 256 * 256; i += stride) {
        int row = i >> 8, co = i & 255;
        float v = 0.f;
        if (row < 240) {
            int k = row / 80, ci = row % 80;
            v = c1w[co * 240 + ci * 3 + k];
        }
        g_w1t[row * 256 + co] = v;
    }
    for (int i = tid; i < 256 * 256 * 3; i += stride) {      // conv2 w
        int k = i % 3, ci = (i / 3) % 256, co = i / 768;
        g_w2t[(k * 256 + ci) * 256 + co] = c2w[i];
    }
    for (int i = tid; i < 2048 * 256; i += stride) {
        int k = i % 256, dr = i / 256;
        g_wih0t[(size_t)k * 2048 + dr] = wih0[i];
    }
    for (int i = tid; i < 2048 * 512; i += stride) {
        int k = i % 512, dr = i / 512;
        g_wih1t[(size_t)k * 2048 + dr] = wih1[i];
    }
    for (int i = tid; i < D_ * D_; i += stride) {
        int d = i / D_, k = i % D_;
        g_wseg1t[k * D_ + d] = segw1[i];
        g_wutt1t[k * D_ + d] = uttw1[i];
    }
    {
        float* p = &g_hstate[0][0][0][0];
        for (int i = tid; i < 2 * 2 * 2 * H_ * B_; i += stride) p[i] = 0.f;
        unsigned* c = &g_cnt[0][0][0];
        for (int i = tid; i < 2 * 2 * 256; i += stride) c[i] = 0u;
    }
}

// ---- permute gproj -> gp2[dir][s][n][b], reversal folded in ----
__global__ void __launch_bounds__(256)
k_permute(const float* __restrict__ gproj, float* __restrict__ gp2,
          const int* __restrict__ len)
{
    __shared__ float tile[32][65];
    __shared__ int Ls[32];
    int s = blockIdx.x, nc = blockIdx.y, dir = blockIdx.z;
    int tid = threadIdx.x;
    if (tid < 32) Ls[tid] = len[tid];
    __syncthreads();

    int b  = tid >> 3;
    int ng = (tid & 7) * 8;
    int L  = Ls[b];
    int t  = dir ? (L - 1 - s) : s;
    bool ok = (s < L);
    int n0 = nc * 64;
    const float* src = gproj + ((size_t)b * T_ + (ok ? t : 0)) * N2_ + dir * 1024 + n0 + ng;
    float4 v0 = make_float4(0.f, 0.f, 0.f, 0.f), v1 = v0;
    if (ok) { v0 = *(const float4*)src; v1 = *(const float4*)(src + 4); }
    tile[b][ng + 0] = v0.x; tile[b][ng + 1] = v0.y;
    tile[b][ng + 2] = v0.z; tile[b][ng + 3] = v0.w;
    tile[b][ng + 4] = v1.x; tile[b][ng + 5] = v1.y;
    tile[b][ng + 6] = v1.z; tile[b][ng + 7] = v1.w;
    __syncthreads();

    float* dst = gp2 + (((size_t)dir * T_ + s) * 1024 + n0) * 32;
    int bb = tid & 31;
#pragma unroll
    for (int i = 0; i < 8; i++) {
        int nl = (tid >> 5) + i * 8;
        dst[(size_t)nl * 32 + bb] = tile[bb][nl];
    }
}

// ---- unpermute houtp[dir][s][u][b] -> hout[b][t][dir*H+u] ----
// Guards s >= L[b] with zeros (scan may stop at maxL; tail of houtp is stale).
__global__ void __launch_bounds__(256)
k_unpermute(const float* __restrict__ houtp, float* __restrict__ hout,
            const int* __restrict__ len)
{
    __shared__ float tile[64][33];
    __shared__ int Ls[32];
    int s = blockIdx.x, uc = blockIdx.y, dir = blockIdx.z;
    int tid = threadIdx.x;
    if (tid < 32) Ls[tid] = len[tid];
    __syncthreads();

    const float* src = houtp + (((size_t)dir * T_ + s) * H_ + uc * 64) * 32;
    int ur = tid >> 5, b = tid & 31;
#pragma unroll
    for (int j = 0; j < 8; j++) {
        int u = ur * 8 + j;
        tile[u][b] = src[(size_t)u * 32 + b];
    }
    __syncthreads();

    int b2 = tid >> 3, ug = tid & 7;
    int L = Ls[b2];
    bool act = (s < L);
    int t = act ? (dir ? (L - 1 - s) : s) : s;
    float v[8];
#pragma unroll
    for (int j = 0; j < 8; j++) v[j] = act ? tile[ug * 8 + j][b2] : 0.f;
    float* dst = hout + ((size_t)b2 * T_ + t) * D_ + dir * H_ + uc * 64 + ug * 8;
    *(float4*)dst       = make_float4(v[0], v[1], v[2], v[3]);
    *(float4*)(dst + 4) = make_float4(v[4], v[5], v[6], v[7]);
}

// ---- tiled SGEMM (f32x2), GBK=32; CI==0: As double + Bs TRIPLE buffer,
//      single __syncthreads per tile ----
#define GBM 128
#define GBN 128
#define GBK 32
#define GEMM_SMEM (5 * GBK * 132 * 4)    // As[2] + Bs[3]

template <int CI>
__global__ void __launch_bounds__(256, 2)
k_gemm(const float* __restrict__ A, const float* __restrict__ Bm,
       const float* __restrict__ bias, float* __restrict__ C,
       int M, int N, int K, int relu)
{
    extern __shared__ float gsm[];
    float (*As)[GBK][132] = (float(*)[GBK][132])gsm;
    float (*Bs)[GBK][132] = (float(*)[GBK][132])(gsm + 2 * GBK * 132);

    int bm = blockIdx.y * GBM;
    int bn = blockIdx.x * GBN;
    int tid = threadIdx.x;
    int tr = tid >> 4;
    int tc = tid & 15;

    ull acc[4][8];
#pragma unroll
    for (int i = 0; i < 4; i++)
#pragma unroll
        for (int j = 0; j < 8; j++) acc[i][j] = 0ull;

    if (CI == 0) {
        // ---- pipelined: B via cp.async (3 buffers), A via reg prefetch (2) ----
        int ntiles = K / GBK;
        float4 areg[4];

#pragma unroll
        for (int i = 0; i < 4; i++) {
            int idx = tid + i * 256;
            int kr = idx >> 5, n4 = (idx & 31) * 4;
            cp16((uint32_t)__cvta_generic_to_shared(&Bs[0][kr][n4]),
                 &Bm[(size_t)kr * N + bn + n4]);
        }
        asm volatile("cp.async.commit_group;");
#pragma unroll
        for (int i = 0; i < 4; i++) {
            int idx = tid + i * 256;
            int row = idx >> 3, c4 = (idx & 7) * 4;
            areg[i] = *(const float4*)&A[(size_t)(bm + row) * K + c4];
        }

        int bufB = 0;
        for (int it = 0; it < ntiles; it++) {
            int bufA = it & 1;
            // store A tile it (from regs, transposed)
#pragma unroll
            for (int i = 0; i < 4; i++) {
                int idx = tid + i * 256;
                int row = idx >> 3, c4 = (idx & 7) * 4;
                As[bufA][c4 + 0][row] = areg[i].x;
                As[bufA][c4 + 1][row] = areg[i].y;
                As[bufA][c4 + 2][row] = areg[i].z;
                As[bufA][c4 + 3][row] = areg[i].w;
            }
            if (it + 1 < ntiles) {
                int k1 = (it + 1) * GBK;
                int nb = bufB + 1; if (nb == 3) nb = 0;
#pragma unroll
                for (int i = 0; i < 4; i++) {
                    int idx = tid + i * 256;
                    int kr = idx >> 5, n4 = (idx & 31) * 4;
                    cp16((uint32_t)__cvta_generic_to_shared(&Bs[nb][kr][n4]),
                         &Bm[(size_t)(k1 + kr) * N + bn + n4]);
                }
                asm volatile("cp.async.commit_group;");
#pragma unroll
                for (int i = 0; i < 4; i++) {
                    int idx = tid + i * 256;
                    int row = idx >> 3, c4 = (idx & 7) * 4;
                    areg[i] = *(const float4*)&A[(size_t)(bm + row) * K + k1 + c4];
                }
                asm volatile("cp.async.wait_group 1;");
            } else {
                asm volatile("cp.async.wait_group 0;");
            }
            __syncthreads();           // single barrier per tile
#pragma unroll 16
            for (int k = 0; k < GBK; k++) {
                ulonglong2 a0 = *(const ulonglong2*)&As[bufA][k][tr * 8];
                ulonglong2 a1 = *(const ulonglong2*)&As[bufA][k][tr * 8 + 4];
                float4 b0 = *(const float4*)&Bs[bufB][k][tc * 4];
                float4 b1 = *(const float4*)&Bs[bufB][k][tc * 4 + 64];
                ull ar0 = a0.x, ar1 = a0.y, ar2 = a1.x, ar3 = a1.y;
                ull bd0 = pack2(b0.x, b0.x), bd1 = pack2(b0.y, b0.y);
                ull bd2 = pack2(b0.z, b0.z), bd3 = pack2(b0.w, b0.w);
                ull bd4 = pack2(b1.x, b1.x), bd5 = pack2(b1.y, b1.y);
                ull bd6 = pack2(b1.z, b1.z), bd7 = pack2(b1.w, b1.w);
                fma2(acc[0][0], ar0, bd0); fma2(acc[0][1], ar0, bd1);
                fma2(acc[0][2], ar0, bd2); fma2(acc[0][3], ar0, bd3);
                fma2(acc[0][4], ar0, bd4); fma2(acc[0][5], ar0, bd5);
                fma2(acc[0][6], ar0, bd6); fma2(acc[0][7], ar0, bd7);
                fma2(acc[1][0], ar1, bd0); fma2(acc[1][1], ar1, bd1);
                fma2(acc[1][2], ar1, bd2); fma2(acc[1][3], ar1, bd3);
                fma2(acc[1][4], ar1, bd4); fma2(acc[1][5], ar1, bd5);
                fma2(acc[1][6], ar1, bd6); fma2(acc[1][7], ar1, bd7);
                fma2(acc[2][0], ar2, bd0); fma2(acc[2][1], ar2, bd1);
                fma2(acc[2][2], ar2, bd2); fma2(acc[2][3], ar2, bd3);
                fma2(acc[2][4], ar2, bd4); fma2(acc[2][5], ar2, bd5);
                fma2(acc[2][6], ar2, bd6); fma2(acc[2][7], ar2, bd7);
                fma2(acc[3][0], ar3, bd0); fma2(acc[3][1], ar3, bd1);
                fma2(acc[3][2], ar3, bd2); fma2(acc[3][3], ar3, bd3);
                fma2(acc[3][4], ar3, bd4); fma2(acc[3][5], ar3, bd5);
                fma2(acc[3][6], ar3, bd6); fma2(acc[3][7], ar3, bd7);
            }
            bufB = bufB + 1; if (bufB == 3) bufB = 0;
        }
    } else {
        // ---- im2col path (convs): synchronous single-buffer ----
        int Kr = (K + GBK - 1) & ~(GBK - 1);
        for (int k0 = 0; k0 < Kr; k0 += GBK) {
#pragma unroll
            for (int i = 0; i < 4; i++) {
                int idx = tid + i * 256;
                int row = idx >> 3;
                int c4 = (idx & 7) * 4;
                int r = bm + row;
                int b = r / T_, t = r % T_;
                int kk = k0 + c4;
                int kt = kk / CI, ci = kk - kt * CI;
                int tt = t + kt - 1;
                float4 v = (kk < K && tt >= 0 && tt < T_)
                    ? *(const float4*)&A[((size_t)b * T_ + tt) * CI + ci]
                    : make_float4(0.f, 0.f, 0.f, 0.f);
                As[0][c4 + 0][row] = v.x;
                As[0][c4 + 1][row] = v.y;
                As[0][c4 + 2][row] = v.z;
                As[0][c4 + 3][row] = v.w;
            }
#pragma unroll
            for (int i = 0; i < 4; i++) {
                int idx = tid + i * 256;
                int kr = idx >> 5;
                int n4 = (idx & 31) * 4;
                *(float4*)&Bs[0][kr][n4] = *(const float4*)&Bm[(size_t)(k0 + kr) * N + bn + n4];
            }
            __syncthreads();
#pragma unroll 16
            for (int k = 0; k < GBK; k++) {
                ulonglong2 a0 = *(const ulonglong2*)&As[0][k][tr * 8];
                ulonglong2 a1 = *(const ulonglong2*)&As[0][k][tr * 8 + 4];
                float4 b0 = *(const float4*)&Bs[0][k][tc * 4];
                float4 b1 = *(const float4*)&Bs[0][k][tc * 4 + 64];
                ull ar0 = a0.x, ar1 = a0.y, ar2 = a1.x, ar3 = a1.y;
                ull bd0 = pack2(b0.x, b0.x), bd1 = pack2(b0.y, b0.y);
                ull bd2 = pack2(b0.z, b0.z), bd3 = pack2(b0.w, b0.w);
                ull bd4 = pack2(b1.x, b1.x), bd5 = pack2(b1.y, b1.y);
                ull bd6 = pack2(b1.z, b1.z), bd7 = pack2(b1.w, b1.w);
                fma2(acc[0][0], ar0, bd0); fma2(acc[0][1], ar0, bd1);
                fma2(acc[0][2], ar0, bd2); fma2(acc[0][3], ar0, bd3);
                fma2(acc[0][4], ar0, bd4); fma2(acc[0][5], ar0, bd5);
                fma2(acc[0][6], ar0, bd6); fma2(acc[0][7], ar0, bd7);
                fma2(acc[1][0], ar1, bd0); fma2(acc[1][1], ar1, bd1);
                fma2(acc[1][2], ar1, bd2); fma2(acc[1][3], ar1, bd3);
                fma2(acc[1][4], ar1, bd4); fma2(acc[1][5], ar1, bd5);
                fma2(acc[1][6], ar1, bd6); fma2(acc[1][7], ar1, bd7);
                fma2(acc[2][0], ar2, bd0); fma2(acc[2][1], ar2, bd1);
                fma2(acc[2][2], ar2, bd2); fma2(acc[2][3], ar2, bd3);
                fma2(acc[2][4], ar2, bd4); fma2(acc[2][5], ar2, bd5);
                fma2(acc[2][6], ar2, bd6); fma2(acc[2][7], ar2, bd7);
                fma2(acc[3][0], ar3, bd0); fma2(acc[3][1], ar3, bd1);
                fma2(acc[3][2], ar3, bd2); fma2(acc[3][3], ar3, bd3);
                fma2(acc[3][4], ar3, bd4); fma2(acc[3][5], ar3, bd5);
                fma2(acc[3][6], ar3, bd6); fma2(acc[3][7], ar3, bd7);
            }
            __syncthreads();
        }
    }

    float bb[8];
    if (bias) {
        float4 bv0 = *(const float4*)&bias[bn + tc * 4];
        float4 bv1 = *(const float4*)&bias[bn + tc * 4 + 64];
        bb[0] = bv0.x; bb[1] = bv0.y; bb[2] = bv0.z; bb[3] = bv0.w;
        bb[4] = bv1.x; bb[5] = bv1.y; bb[6] = bv1.z; bb[7] = bv1.w;
    } else {
#pragma unroll
        for (int c = 0; c < 8; c++) bb[c] = 0.f;
    }
#pragma unroll
    for (int rp = 0; rp < 4; rp++) {
        float o0[8], o1[8];
#pragma unroll
        for (int c = 0; c < 8; c++) {
            float2 u = unpack2(acc[rp][c]);
            o0[c] = u.x + bb[c];
            o1[c] = u.y + bb[c];
            if (relu) { o0[c] = fmaxf(o0[c], 0.f); o1[c] = fmaxf(o1[c], 0.f); }
        }
        int row0 = bm + tr * 8 + rp * 2;
        float* p0 = &C[(size_t)row0 * N + bn];
        float* p1 = p0 + N;
        *(float4*)(p0 + tc * 4)      = make_float4(o0[0], o0[1], o0[2], o0[3]);
        *(float4*)(p0 + tc * 4 + 64) = make_float4(o0[4], o0[5], o0[6], o0[7]);
        *(float4*)(p1 + tc * 4)      = make_float4(o1[0], o1[1], o1[2], o1[3]);
        *(float4*)(p1 + tc * 4 + 64) = make_float4(o1[4], o1[5], o1[6], o1[7]);
    }
}

// ------------------- persistent BiLSTM scan (one layer, both dirs) ----------
// R12 proven version (quarter-scoped barrier) + early exit at maxL.
#define SCAN_NCTA 128
#define SCAN_SMEM ((8192 + 8192 + 2048) * 4 + 128)

__global__ void __launch_bounds__(256, 1)
k_scan(const float* __restrict__ gp2, const float* __restrict__ whh,
       const int* __restrict__ lengths, float* __restrict__ houtp, int layer)
{
    extern __shared__ float sm[];
    ull*   w2  = (ull*)sm;                 // [256][16] dup'd weights (32 KB)
    float* h_s = sm + 8192;                // [256][32] h (k-major, 32 KB)
    float* g_p = sm + 16384;               // [4][16][32] partial gates (8 KB)
    int*   L_s = (int*)(sm + 18432);       // [32]

    const int bid = blockIdx.x;
    const int dir = bid >> 6;
    const int u0  = (bid & 63) * 4;
    const int tid = threadIdx.x;
    const int smax = *(volatile int*)&g_maxL;

    for (int i = tid; i < 4096; i += 256) {
        int k = i >> 4, r = i & 15;
        int q = r >> 2, j = r & 3;
        float w = whh[(size_t)dir * 262144 + (size_t)(q * 256 + u0 + j) * 256 + k];
        w2[(size_t)k * 16 + r] = pack2(w, w);
    }
    if (tid < 32) L_s[tid] = lengths[tid];
    __syncthreads();

    const int kq = tid >> 6;             // k-quarter this group consumes
    const int jown = (bid & 63) >> 4;    // h-quarter this CTA produces
    const int rp = (tid & 63) >> 3;      // row pair 0..7
    const int b4 = tid & 7;              // batch quad 0..7
    const int cu = (tid >> 5) & 3;       // unit 0..3 (gate phase, tid<128)
    const int cb = tid & 31;             // batch   (gate phase, tid<128)
    const bool gthr = tid < 128;
    const bool poller = (tid & 63) == 0;
    const int Lcb = L_s[cb];
    float creg = 0.f;

    unsigned* arrive_cnt = &g_cnt[layer][dir][jown * 64];
    unsigned* poll_cnt   = &g_cnt[layer][dir][kq * 64];

    const float* gbase = gp2 + ((size_t)dir * T_ * 1024 + u0 + cu) * 32 + cb;
    float* hpo = houtp + ((size_t)dir * T_ * H_ + u0 + cu) * 32 + cb;

    for (int s = 0; s < smax; s++) {
        bool act = s < Lcb;

        // prefetch gates for this step (DRAM; consumed ~2k cyc later)
        float pi = 0.f, pf = 0.f, pg = 0.f, po = 0.f;
        if (gthr) {
            const float* gp = gbase + (size_t)s * 1024 * 32;
            pi = __ldcg(gp);
            pf = __ldcg(gp + 256 * 32);
            pg = __ldcg(gp + 512 * 32);
            po = __ldcg(gp + 768 * 32);
        }

        // wait only for the 16 producers of OUR quarter, then load it
        if (poller && s > 0) {
            unsigned tgt = (unsigned)s * 16u;
            while (ld_acq(poll_cnt) < tgt) { }
        }
        asm volatile("bar.sync %0, 64;" :: "r"(1 + kq) : "memory");
        {
            const float* hsrc = g_hstate[layer][s & 1][dir] + kq * 2048;
            float*       hdst = h_s + kq * 2048;
            int lt = tid & 63;
#pragma unroll
            for (int i = 0; i < 8; i++) {
                int idx = (lt + i * 64) * 4;
                *(float4*)(hdst + idx) = __ldcg((const float4*)(hsrc + idx));
            }
        }
        asm volatile("bar.sync %0, 64;" :: "r"(1 + kq) : "memory");

        // dot: rows (2rp,2rp+1) x batches (4b4..+3) over k-quarter, all FFMA2
        ull a00 = 0ull, a01 = 0ull, a10 = 0ull, a11 = 0ull;
        const ull*   wp = w2 + (size_t)(kq * 64) * 16 + rp * 2;
        const float* hp = h_s + (kq * 64) * 32 + b4 * 4;
#pragma unroll 8
        for (int k = 0; k < 64; k++) {
            ulonglong2 w = *(const ulonglong2*)wp;
            ulonglong2 h = *(const ulonglong2*)hp;
            fma2(a00, w.x, h.x); fma2(a01, w.x, h.y);
            fma2(a10, w.y, h.x); fma2(a11, w.y, h.y);
            wp += 16; hp += 32;
        }
        {
            float* gp0 = g_p + kq * 512 + (rp * 2) * 32 + b4 * 4;
            float2 u;
            u = unpack2(a00); gp0[0] = u.x; gp0[1] = u.y;
            u = unpack2(a01); gp0[2] = u.x; gp0[3] = u.y;
            float* gp1 = gp0 + 32;
            u = unpack2(a10); gp1[0] = u.x; gp1[1] = u.y;
            u = unpack2(a11); gp1[2] = u.x; gp1[3] = u.y;
        }
        __syncthreads();

        // gates + state update; thread (unit cu, batch cb), tid<128
        float h = 0.f;
        if (gthr && act) {
            float gi = pi, gf = pf, gg = pg, go = po;
#pragma unroll
            for (int q = 0; q < 4; q++) {
                gi += g_p[q * 512 + (cu)      * 32 + cb];
                gf += g_p[q * 512 + (4 + cu)  * 32 + cb];
                gg += g_p[q * 512 + (8 + cu)  * 32 + cb];
                go += g_p[q * 512 + (12 + cu) * 32 + cb];
            }
            gi = sig_fast(gi);
            gf = sig_fast(gf);
            go = sig_fast(go);
            gg = tanh_fast(gg);
            creg = gf * creg + gi * gg;
            h = go * tanh_fast(creg);
            __stcg(&g_hstate[layer][(s & 1) ^ 1][dir][(u0 + cu) * 32 + cb], h);
        }
        if (gthr) __stcg(hpo + (size_t)s * H_ * 32, h);

        // publish arrival for the quarter we produce
        __syncthreads();
        if (tid == 0) red_rel(arrive_cnt);
    }
}

// ------------------- pooling + heads -------------------
__global__ void k_pool(const float* __restrict__ hout, const int* __restrict__ len,
                       float* __restrict__ pooled) {
    int b = blockIdx.x;
    int c = blockIdx.y * 128 + threadIdx.x;
    float s = 0.f;
    const float* p = hout + (size_t)b * T_ * D_ + c;
    for (int t = 0; t < T_; t++) s += p[(size_t)t * D_];
    int L = len[b];
    pooled[b * D_ + c] = s / (float)(L > 1 ? L : 1);
}

__global__ void k_utt(const float* __restrict__ pooled, const float* __restrict__ w1t,
                      const float* __restrict__ b1, const float* __restrict__ w2,
                      const float* __restrict__ b2, float* __restrict__ out) {
    int b = blockIdx.x, d = threadIdx.x;
    __shared__ float ps[D_];
    __shared__ float red[D_];
    ps[d] = pooled[b * D_ + d];
    __syncthreads();
    float acc = b1[d];
    for (int k = 0; k < D_; k++) acc = fmaf(ps[k], w1t[k * D_ + d], acc);
    red[d] = fmaxf(acc, 0.f) * w2[d];
    __syncthreads();
    for (int st = 256; st > 0; st >>= 1) {
        if (d < st) red[d] += red[d + st];
        __syncthreads();
    }
    if (d == 0) out[b] = red[0] + b2[0];
}

__global__ void k_seg(const float* __restrict__ hout, const int* __restrict__ segs,
                      const int* __restrict__ len, const int* __restrict__ seglen,
                      const float* __restrict__ w1t, const float* __restrict__ b1,
                      const float* __restrict__ w2, const float* __restrict__ b2,
                      float* __restrict__ out) {
    int si = blockIdx.x, b = blockIdx.y, d = threadIdx.x;
    __shared__ float mean_s[D_];
    __shared__ float red[D_];
    int L = len[b];
    int s0 = segs[(b * S_ + si) * 2 + 0];
    int e0 = segs[(b * S_ + si) * 2 + 1];
    int s = min(max(s0, 0), L);
    int e = max(s + 1, min(e0, L));
    float cnt = (float)(e - s);
    int ec = min(e, T_);
    float acc = 0.f;
    const float* p = hout + ((size_t)b * T_ + s) * D_ + d;
    for (int t = s; t < ec; t++, p += D_) acc += *p;
    mean_s[d] = acc / cnt;
    __syncthreads();
    float hv = b1[d];
    for (int k = 0; k < D_; k++) hv = fmaf(mean_s[k], w1t[k * D_ + d], hv);
    red[d] = fmaxf(hv, 0.f) * w2[d];
    __syncthreads();
    for (int st = 256; st > 0; st >>= 1) {
        if (d < st) red[d] += red[d + st];
        __syncthreads();
    }
    if (d == 0) {
        float sc = red[0] + b2[0];
        out[B_ + b * S_ + si] = (si < seglen[b]) ? sc : 0.f;
    }
}

// ------------------- driver -------------------
extern "C" void kernel_launch(void* const* d_in, const int* in_sizes, int n_in,
                              void* d_out, int out_size) {
    const float* features = (const float*)d_in[0];
    const int*   feat_len = (const int*)d_in[1];
    const int*   segs     = (const int*)d_in[2];
    const int*   seg_len  = (const int*)d_in[3];
    const float* conv1_w  = (const float*)d_in[4];
    const float* conv1_b  = (const float*)d_in[5];
    const float* conv2_w  = (const float*)d_in[6];
    const float* conv2_b  = (const float*)d_in[7];
    const float* wih0     = (const float*)d_in[8];
    const float* whh0     = (const float*)d_in[9];
    const float* bias0    = (const float*)d_in[10];
    const float* wih1     = (const float*)d_in[11];
    const float* whh1     = (const float*)d_in[12];
    const float* bias1    = (const float*)d_in[13];
    const float* seg_w1   = (const float*)d_in[14];
    const float* seg_b1   = (const float*)d_in[15];
    const float* seg_w2   = (const float*)d_in[16];
    const float* seg_b2   = (const float*)d_in[17];
    const float* utt_w1   = (const float*)d_in[18];
    const float* utt_b1   = (const float*)d_in[19];
    const float* utt_w2   = (const float*)d_in[20];
    const float* utt_b2   = (const float*)d_in[21];
    float* out = (float*)d_out;

    cudaFuncSetAttribute(k_scan, cudaFuncAttributeMaxDynamicSharedMemorySize, SCAN_SMEM);
    cudaFuncSetAttribute(k_gemm<0>,   cudaFuncAttributeMaxDynamicSharedMemorySize, GEMM_SMEM);
    cudaFuncSetAttribute(k_gemm<80>,  cudaFuncAttributeMaxDynamicSharedMemorySize, GEMM_SMEM);
    cudaFuncSetAttribute(k_gemm<256>, cudaFuncAttributeMaxDynamicSharedMemorySize, GEMM_SMEM);

    float *x1, *x2, *gproj, *gp2, *houtp, *hout0, *hout1, *w1t, *w2t,
          *wih0t, *wih1t, *wseg1t, *wutt1t, *pooled;
    cudaGetSymbolAddress((void**)&x1,     g_x1);
    cudaGetSymbolAddress((void**)&x2,     g_x2);
    cudaGetSymbolAddress((void**)&gproj,  g_gproj);
    cudaGetSymbolAddress((void**)&gp2,    g_gp2);
    cudaGetSymbolAddress((void**)&houtp,  g_houtp);
    cudaGetSymbolAddress((void**)&hout0,  g_hout0);
    cudaGetSymbolAddress((void**)&hout1,  g_hout1);
    cudaGetSymbolAddress((void**)&w1t,    g_w1t);
    cudaGetSymbolAddress((void**)&w2t,    g_w2t);
    cudaGetSymbolAddress((void**)&wih0t,  g_wih0t);
    cudaGetSymbolAddress((void**)&wih1t,  g_wih1t);
    cudaGetSymbolAddress((void**)&wseg1t, g_wseg1t);
    cudaGetSymbolAddress((void**)&wutt1t, g_wutt1t);
    cudaGetSymbolAddress((void**)&pooled, g_pooled);

    // 1: fused prep (+ maxL)
    k_prep<<<2048, 256>>>(conv1_w, conv2_w, wih0, wih1, seg_w1, utt_w1, feat_len);
    // 2: conv1 (im2col fused, K=240 padded weights)
    k_gemm<80><<<dim3(256/GBN, M_/GBM), 256, GEMM_SMEM>>>(features, w1t, conv1_b, x1, M_, 256, 240, 1);
    // 3: conv2 (im2col fused)
    k_gemm<256><<<dim3(256/GBN, M_/GBM), 256, GEMM_SMEM>>>(x1, w2t, conv2_b, x2, M_, 256, 768, 1);
    // 4: layer-0 input projection
    k_gemm<0><<<dim3(N2_/GBN, M_/GBM), 256, GEMM_SMEM>>>(x2, wih0t, bias0, gproj, M_, N2_, 256, 0);
    // 5: permute gproj (reversal folded in)
    k_permute<<<dim3(T_, 16, 2), 256>>>(gproj, gp2, feat_len);
    // 6: layer-0 scan
    k_scan<<<SCAN_NCTA, 256, SCAN_SMEM>>>(gp2, whh0, feat_len, houtp, 0);
    // 7: unpermute layer-0 output
    k_unpermute<<<dim3(T_, 4, 2), 256>>>(houtp, hout0, feat_len);
    // 8: layer-1 input projection
    k_gemm<0><<<dim3(N2_/GBN, M_/GBM), 256, GEMM_SMEM>>>(hout0, wih1t, bias1, gproj, M_, N2_, 512, 0);
    // 9: permute
    k_permute<<<dim3(T_, 16, 2), 256>>>(gproj, gp2, feat_len);
    // 10: layer-1 scan
    k_scan<<<SCAN_NCTA, 256, SCAN_SMEM>>>(gp2, whh1, feat_len, houtp, 1);
    // 11: unpermute layer-1 output
    k_unpermute<<<dim3(T_, 4, 2), 256>>>(houtp, hout1, feat_len);

    // pooling + heads
    k_pool<<<dim3(B_, 4), 128>>>(hout1, feat_len, pooled);
    k_utt<<<B_, D_>>>(pooled, wutt1t, utt_b1, utt_w2, utt_b2, out);
    k_seg<<<dim3(S_, B_), D_>>>(hout1, segs, feat_len, seg_len,
                                wseg1t, seg_b1, seg_w2, seg_b2, out);
}

// round 15
// speedup vs baseline: 1.0614x; 1.0416x over previous
#include <cuda_runtime.h>
#include <cuda_bf16.h>
#include <cstdint>

#define B_    32
#define T_    2000
#define F_    80
#define H_    256
#define S_    100
#define D_    512        // 2*H
#define M_    (B_*T_)    // 64000
#define N2_   2048       // 2 dirs * 4H

typedef unsigned long long ull;

// ------------------- packed f32x2 helpers (FFMA2) -------------------
__device__ __forceinline__ ull pack2(float x, float y) {
    ull r; asm("mov.b64 %0, {%1, %2};" : "=l"(r) : "f"(x), "f"(y)); return r;
}
__device__ __forceinline__ float2 unpack2(ull v) {
    float2 r; asm("mov.b64 {%0, %1}, %2;" : "=f"(r.x), "=f"(r.y) : "l"(v)); return r;
}
__device__ __forceinline__ void fma2(ull& d, ull a, ull b) {
    asm("fma.rn.f32x2 %0, %1, %2, %0;" : "+l"(d) : "l"(a), "l"(b));
}
__device__ __forceinline__ float rcpa(float x) {
    float r; asm("rcp.approx.f32 %0, %1;" : "=f"(r) : "f"(x)); return r;
}
__device__ __forceinline__ float sig_fast(float x) {
    return rcpa(1.f + __expf(-x));
}
__device__ __forceinline__ float tanh_fast(float x) {
    float e = __expf(2.f * x);
    return 1.f - 2.f * rcpa(e + 1.f);
}
__device__ __forceinline__ unsigned ld_acq(const unsigned* p) {
    unsigned v;
    asm volatile("ld.acquire.gpu.global.u32 %0, [%1];" : "=r"(v) : "l"(p) : "memory");
    return v;
}
__device__ __forceinline__ void red_rel(unsigned* p) {
    asm volatile("red.release.gpu.global.add.u32 [%0], 1;" :: "l"(p) : "memory");
}
__device__ __forceinline__ void cp16(uint32_t dst, const void* src) {
    asm volatile("cp.async.cg.shared.global [%0], [%1], 16;" :: "r"(dst), "l"(src));
}

// ------------------- scratch (static __device__, no allocs) -------------------
__device__ float g_x1 [(size_t)M_*256];          // conv1 out
__device__ float g_x2 [(size_t)M_*256];          // conv2 out
__device__ float g_gproj[(size_t)M_*N2_];        // input projections (reused L0/L1)
__device__ float g_gp2  [(size_t)2*T_*1024*B_];  // permuted [dir][s][n][b]
__device__ float g_houtp[(size_t)2*T_*H_*B_];    // scan out [dir][s][u][b]
__device__ float g_hout0[(size_t)M_*D_];         // layer0 bilstm out [b][t][d]
__device__ float g_hout1[(size_t)M_*D_];         // layer1 bilstm out
__device__ float g_w1t [256*256];                // padded K 240->256 (zero rows)
__device__ float g_w2t [768*256];
__device__ float g_wih0t[(size_t)256*N2_];
__device__ float g_wih1t[(size_t)512*N2_];
__device__ float g_wseg1t[D_*D_];
__device__ float g_wutt1t[D_*D_];
__device__ float g_pooled[B_*D_];
// [layer][buf][dir][bg*4096 + u*16 + cbl]
__device__ float g_hstate[2][2][2][H_*B_];
__device__ unsigned g_cnt[2][2][512];            // [layer][dir][(bg*4+quarter)*64]

// ------------------- fused prep: all transposes + state zeroing -------------
__global__ void k_prep(const float* __restrict__ c1w, const float* __restrict__ c2w,
                       const float* __restrict__ wih0, const float* __restrict__ wih1,
                       const float* __restrict__ segw1, const float* __restrict__ uttw1)
{
    int stride = gridDim.x * blockDim.x;
    int tid = blockIdx.x * blockDim.x + threadIdx.x;

    // conv1 w: [Co][Ci][3] -> [3*Ci][Co], rows 240..255 zero (K padded to 256)
    for (int i = tid; i < 256 * 256; i += stride) {
        int row = i >> 8, co = i & 255;
        float v = 0.f;
        if (row < 240) {
            int k = row / 80, ci = row % 80;
            v = c1w[co * 240 + ci * 3 + k];
        }
        g_w1t[row * 256 + co] = v;
    }
    for (int i = tid; i < 256 * 256 * 3; i += stride) {      // conv2 w
        int k = i % 3, ci = (i / 3) % 256, co = i / 768;
        g_w2t[(k * 256 + ci) * 256 + co] = c2w[i];
    }
    for (int i = tid; i < 2048 * 256; i += stride) {
        int k = i % 256, dr = i / 256;
        g_wih0t[(size_t)k * 2048 + dr] = wih0[i];
    }
    for (int i = tid; i < 2048 * 512; i += stride) {
        int k = i % 512, dr = i / 512;
        g_wih1t[(size_t)k * 2048 + dr] = wih1[i];
    }
    for (int i = tid; i < D_ * D_; i += stride) {
        int d = i / D_, k = i % D_;
        g_wseg1t[k * D_ + d] = segw1[i];
        g_wutt1t[k * D_ + d] = uttw1[i];
    }
    {
        float* p = &g_hstate[0][0][0][0];
        for (int i = tid; i < 2 * 2 * 2 * H_ * B_; i += stride) p[i] = 0.f;
        unsigned* c = &g_cnt[0][0][0];
        for (int i = tid; i < 2 * 2 * 512; i += stride) c[i] = 0u;
    }
}

// ---- permute gproj -> gp2[dir][s][n][b], reversal folded in ----
__global__ void __launch_bounds__(256)
k_permute(const float* __restrict__ gproj, float* __restrict__ gp2,
          const int* __restrict__ len)
{
    __shared__ float tile[32][65];
    __shared__ int Ls[32];
    int s = blockIdx.x, nc = blockIdx.y, dir = blockIdx.z;
    int tid = threadIdx.x;
    if (tid < 32) Ls[tid] = len[tid];
    __syncthreads();

    int b  = tid >> 3;
    int ng = (tid & 7) * 8;
    int L  = Ls[b];
    int t  = dir ? (L - 1 - s) : s;
    bool ok = (s < L);
    int n0 = nc * 64;
    const float* src = gproj + ((size_t)b * T_ + (ok ? t : 0)) * N2_ + dir * 1024 + n0 + ng;
    float4 v0 = make_float4(0.f, 0.f, 0.f, 0.f), v1 = v0;
    if (ok) { v0 = *(const float4*)src; v1 = *(const float4*)(src + 4); }
    tile[b][ng + 0] = v0.x; tile[b][ng + 1] = v0.y;
    tile[b][ng + 2] = v0.z; tile[b][ng + 3] = v0.w;
    tile[b][ng + 4] = v1.x; tile[b][ng + 5] = v1.y;
    tile[b][ng + 6] = v1.z; tile[b][ng + 7] = v1.w;
    __syncthreads();

    float* dst = gp2 + (((size_t)dir * T_ + s) * 1024 + n0) * 32;
    int bb = tid & 31;
#pragma unroll
    for (int i = 0; i < 8; i++) {
        int nl = (tid >> 5) + i * 8;
        dst[(size_t)nl * 32 + bb] = tile[bb][nl];
    }
}

// ---- unpermute houtp[dir][s][u][b] -> hout[b][t][dir*H+u] ----
// Guards s >= L[b] with zeros (scan stops at per-domain maxL; tail is stale).
__global__ void __launch_bounds__(256)
k_unpermute(const float* __restrict__ houtp, float* __restrict__ hout,
            const int* __restrict__ len)
{
    __shared__ float tile[64][33];
    __shared__ int Ls[32];
    int s = blockIdx.x, uc = blockIdx.y, dir = blockIdx.z;
    int tid = threadIdx.x;
    if (tid < 32) Ls[tid] = len[tid];
    __syncthreads();

    const float* src = houtp + (((size_t)dir * T_ + s) * H_ + uc * 64) * 32;
    int ur = tid >> 5, b = tid & 31;
#pragma unroll
    for (int j = 0; j < 8; j++) {
        int u = ur * 8 + j;
        tile[u][b] = src[(size_t)u * 32 + b];
    }
    __syncthreads();

    int b2 = tid >> 3, ug = tid & 7;
    int L = Ls[b2];
    bool act = (s < L);
    int t = act ? (dir ? (L - 1 - s) : s) : s;
    float v[8];
#pragma unroll
    for (int j = 0; j < 8; j++) v[j] = act ? tile[ug * 8 + j][b2] : 0.f;
    float* dst = hout + ((size_t)b2 * T_ + t) * D_ + dir * H_ + uc * 64 + ug * 8;
    *(float4*)dst       = make_float4(v[0], v[1], v[2], v[3]);
    *(float4*)(dst + 4) = make_float4(v[4], v[5], v[6], v[7]);
}

// ---- tiled SGEMM (f32x2), GBK=32; As double + Bs triple buffer,
//      single __syncthreads per tile; A from plain (CI=0) or im2col gather ----
#define GBM 128
#define GBN 128
#define GBK 32
#define GEMM_SMEM (5 * GBK * 132 * 4)    // As[2] + Bs[3]

template <int CI>
__global__ void __launch_bounds__(256, 2)
k_gemm(const float* __restrict__ A, const float* __restrict__ Bm,
       const float* __restrict__ bias, float* __restrict__ C,
       int M, int N, int K, int relu)
{
    extern __shared__ float gsm[];
    float (*As)[GBK][132] = (float(*)[GBK][132])gsm;
    float (*Bs)[GBK][132] = (float(*)[GBK][132])(gsm + 2 * GBK * 132);

    int bm = blockIdx.y * GBM;
    int bn = blockIdx.x * GBN;
    int tid = threadIdx.x;
    int tr = tid >> 4;
    int tc = tid & 15;

    ull acc[4][8];
#pragma unroll
    for (int i = 0; i < 4; i++)
#pragma unroll
        for (int j = 0; j < 8; j++) acc[i][j] = 0ull;

    int Kr = (K + GBK - 1) & ~(GBK - 1);
    int ntiles = Kr / GBK;
    float4 areg[4];

    // A gather (plain or im2col) into registers
    auto loadA = [&](int k0) {
#pragma unroll
        for (int i = 0; i < 4; i++) {
            int idx = tid + i * 256;
            int row = idx >> 3, c4 = (idx & 7) * 4;
            if (CI == 0) {
                areg[i] = *(const float4*)&A[(size_t)(bm + row) * K + k0 + c4];
            } else {
                int r = bm + row;
                int b = r / T_, t = r % T_;
                int kk = k0 + c4;
                int kt = kk / CI, ci = kk - kt * CI;
                int tt = t + kt - 1;
                areg[i] = (kk < K && tt >= 0 && tt < T_)
                    ? *(const float4*)&A[((size_t)b * T_ + tt) * CI + ci]
                    : make_float4(0.f, 0.f, 0.f, 0.f);
            }
        }
    };

    // prologue: B tile 0 via cp.async, A tile 0 to regs
#pragma unroll
    for (int i = 0; i < 4; i++) {
        int idx = tid + i * 256;
        int kr = idx >> 5, n4 = (idx & 31) * 4;
        cp16((uint32_t)__cvta_generic_to_shared(&Bs[0][kr][n4]),
             &Bm[(size_t)kr * N + bn + n4]);
    }
    asm volatile("cp.async.commit_group;");
    loadA(0);

    int bufB = 0;
    for (int it = 0; it < ntiles; it++) {
        int bufA = it & 1;
#pragma unroll
        for (int i = 0; i < 4; i++) {
            int idx = tid + i * 256;
            int row = idx >> 3, c4 = (idx & 7) * 4;
            As[bufA][c4 + 0][row] = areg[i].x;
            As[bufA][c4 + 1][row] = areg[i].y;
            As[bufA][c4 + 2][row] = areg[i].z;
            As[bufA][c4 + 3][row] = areg[i].w;
        }
        if (it + 1 < ntiles) {
            int k1 = (it + 1) * GBK;
            int nb = bufB + 1; if (nb == 3) nb = 0;
#pragma unroll
            for (int i = 0; i < 4; i++) {
                int idx = tid + i * 256;
                int kr = idx >> 5, n4 = (idx & 31) * 4;
                cp16((uint32_t)__cvta_generic_to_shared(&Bs[nb][kr][n4]),
                     &Bm[(size_t)(k1 + kr) * N + bn + n4]);
            }
            asm volatile("cp.async.commit_group;");
            loadA(k1);
            asm volatile("cp.async.wait_group 1;");
        } else {
            asm volatile("cp.async.wait_group 0;");
        }
        __syncthreads();           // single barrier per tile
#pragma unroll 16
        for (int k = 0; k < GBK; k++) {
            ulonglong2 a0 = *(const ulonglong2*)&As[bufA][k][tr * 8];
            ulonglong2 a1 = *(const ulonglong2*)&As[bufA][k][tr * 8 + 4];
            float4 b0 = *(const float4*)&Bs[bufB][k][tc * 4];
            float4 b1 = *(const float4*)&Bs[bufB][k][tc * 4 + 64];
            ull ar0 = a0.x, ar1 = a0.y, ar2 = a1.x, ar3 = a1.y;
            ull bd0 = pack2(b0.x, b0.x), bd1 = pack2(b0.y, b0.y);
            ull bd2 = pack2(b0.z, b0.z), bd3 = pack2(b0.w, b0.w);
            ull bd4 = pack2(b1.x, b1.x), bd5 = pack2(b1.y, b1.y);
            ull bd6 = pack2(b1.z, b1.z), bd7 = pack2(b1.w, b1.w);
            fma2(acc[0][0], ar0, bd0); fma2(acc[0][1], ar0, bd1);
            fma2(acc[0][2], ar0, bd2); fma2(acc[0][3], ar0, bd3);
            fma2(acc[0][4], ar0, bd4); fma2(acc[0][5], ar0, bd5);
            fma2(acc[0][6], ar0, bd6); fma2(acc[0][7], ar0, bd7);
            fma2(acc[1][0], ar1, bd0); fma2(acc[1][1], ar1, bd1);
            fma2(acc[1][2], ar1, bd2); fma2(acc[1][3], ar1, bd3);
            fma2(acc[1][4], ar1, bd4); fma2(acc[1][5], ar1, bd5);
            fma2(acc[1][6], ar1, bd6); fma2(acc[1][7], ar1, bd7);
            fma2(acc[2][0], ar2, bd0); fma2(acc[2][1], ar2, bd1);
            fma2(acc[2][2], ar2, bd2); fma2(acc[2][3], ar2, bd3);
            fma2(acc[2][4], ar2, bd4); fma2(acc[2][5], ar2, bd5);
            fma2(acc[2][6], ar2, bd6); fma2(acc[2][7], ar2, bd7);
            fma2(acc[3][0], ar3, bd0); fma2(acc[3][1], ar3, bd1);
            fma2(acc[3][2], ar3, bd2); fma2(acc[3][3], ar3, bd3);
            fma2(acc[3][4], ar3, bd4); fma2(acc[3][5], ar3, bd5);
            fma2(acc[3][6], ar3, bd6); fma2(acc[3][7], ar3, bd7);
        }
        bufB = bufB + 1; if (bufB == 3) bufB = 0;
    }

    float bb[8];
    if (bias) {
        float4 bv0 = *(const float4*)&bias[bn + tc * 4];
        float4 bv1 = *(const float4*)&bias[bn + tc * 4 + 64];
        bb[0] = bv0.x; bb[1] = bv0.y; bb[2] = bv0.z; bb[3] = bv0.w;
        bb[4] = bv1.x; bb[5] = bv1.y; bb[6] = bv1.z; bb[7] = bv1.w;
    } else {
#pragma unroll
        for (int c = 0; c < 8; c++) bb[c] = 0.f;
    }
#pragma unroll
    for (int rp = 0; rp < 4; rp++) {
        float o0[8], o1[8];
#pragma unroll
        for (int c = 0; c < 8; c++) {
            float2 u = unpack2(acc[rp][c]);
            o0[c] = u.x + bb[c];
            o1[c] = u.y + bb[c];
            if (relu) { o0[c] = fmaxf(o0[c], 0.f); o1[c] = fmaxf(o1[c], 0.f); }
        }
        int row0 = bm + tr * 8 + rp * 2;
        float* p0 = &C[(size_t)row0 * N + bn];
        float* p1 = p0 + N;
        *(float4*)(p0 + tc * 4)      = make_float4(o0[0], o0[1], o0[2], o0[3]);
        *(float4*)(p0 + tc * 4 + 64) = make_float4(o0[4], o0[5], o0[6], o0[7]);
        *(float4*)(p1 + tc * 4)      = make_float4(o1[0], o1[1], o1[2], o1[3]);
        *(float4*)(p1 + tc * 4 + 64) = make_float4(o1[4], o1[5], o1[6], o1[7]);
    }
}

// ------------------- persistent BiLSTM scan (one layer, both dirs) ----------
// BATCH-SPLIT: 128 CTAs = 2 dirs x 2 batch-groups(16) x 32 unit-chunks(8u).
// Each CTA: 8 units x 16 batches; 4 k-groups of 64 threads consume the 4
// h-quarters of their (dir,bg) domain (32 CTAs, 8 producers/counter).
#define SCAN_NCTA 128
#define SCAN_SMEM ((16384 + 4096 + 2048) * 4 + 128)

__global__ void __launch_bounds__(256, 1)
k_scan(const float* __restrict__ gp2, const float* __restrict__ whh,
       const int* __restrict__ lengths, float* __restrict__ houtp, int layer)
{
    extern __shared__ float sm[];
    ull*   w2  = (ull*)sm;                 // [256 k][32 r] dup'd weights (64 KB)
    float* h_s = sm + 16384;               // [256 k][16 b] (16 KB)
    float* g_p = sm + 20480;               // [4][32 r][16 b] partials (8 KB)
    int*   L_s = (int*)(sm + 22528);       // [16]

    const int bid = blockIdx.x;
    const int dir = bid >> 6;
    const int wd  = bid & 63;
    const int bg  = wd >> 5;               // batch group 0/1
    const int cg  = wd & 31;               // unit chunk 0..31
    const int ug0 = cg * 8;                // first of 8 units
    const int tid = threadIdx.x;

    // weights: local row r = q*8+j (gate q, unit j) <-> whh row q*256+ug0+j
    for (int i = tid; i < 8192; i += 256) {
        int k = i >> 5, r = i & 31;
        int q = r >> 3, j = r & 7;
        float w = whh[(size_t)dir * 262144 + (size_t)(q * 256 + ug0 + j) * 256 + k];
        w2[(size_t)k * 32 + r] = pack2(w, w);
    }
    if (tid < 16) L_s[tid] = lengths[bg * 16 + tid];
    __syncthreads();

    int smax = 1;
#pragma unroll
    for (int i = 0; i < 16; i++) smax = max(smax, L_s[i]);

    const int kq = tid >> 6;             // k-quarter this group consumes
    const int lt = tid & 63;
    const int rp = lt >> 2;              // row pair 0..15 (rows 2rp, 2rp+1)
    const int b4 = lt & 3;               // batch quad 0..3 (local)
    const int jown = cg >> 3;            // h-quarter this CTA produces
    const int cu  = (tid >> 4) & 7;      // unit 0..7   (gate phase, tid<128)
    const int cbl = tid & 15;            // local batch (gate phase, tid<128)
    const bool gthr = tid < 128;
    const bool poller = (lt == 0);
    const int Lcb = L_s[cbl];
    float creg = 0.f;

    unsigned* arrive_cnt = &g_cnt[layer][dir][(bg * 4 + jown) * 64];
    unsigned* poll_cnt   = &g_cnt[layer][dir][(bg * 4 + kq) * 64];

    const float* gbase = gp2 + ((size_t)dir * T_ * 1024 + ug0 + cu) * 32 + bg * 16 + cbl;
    float* hpo = houtp + ((size_t)dir * T_ * H_ + ug0 + cu) * 32 + bg * 16 + cbl;
    const int hsoff = bg * 4096;

    for (int s = 0; s < smax; s++) {
        bool act = s < Lcb;

        // prefetch gates for this step
        float pi = 0.f, pf = 0.f, pg = 0.f, po = 0.f;
        if (gthr) {
            const float* gp = gbase + (size_t)s * 1024 * 32;
            pi = __ldcg(gp);
            pf = __ldcg(gp + 256 * 32);
            pg = __ldcg(gp + 512 * 32);
            po = __ldcg(gp + 768 * 32);
        }

        // wait for the 8 producers of OUR quarter, then load it (4 KB)
        if (poller && s > 0) {
            unsigned tgt = (unsigned)s * 8u;
            while (ld_acq(poll_cnt) < tgt) { }
        }
        asm volatile("bar.sync %0, 64;" :: "r"(1 + kq) : "memory");
        {
            const float* hsrc = &g_hstate[layer][s & 1][dir][hsoff + kq * 1024];
            float*       hdst = h_s + kq * 1024;
#pragma unroll
            for (int i = 0; i < 4; i++) {
                int idx = (lt + i * 64) * 4;
                *(float4*)(hdst + idx) = __ldcg((const float4*)(hsrc + idx));
            }
        }
        asm volatile("bar.sync %0, 64;" :: "r"(1 + kq) : "memory");

        // dot: rows (2rp,2rp+1) x local batches (4b4..+3) over k-quarter
        ull a00 = 0ull, a01 = 0ull, a10 = 0ull, a11 = 0ull;
        const ull*   wp = w2 + (size_t)(kq * 64) * 32 + rp * 2;
        const float* hp = h_s + (kq * 64) * 16 + b4 * 4;
#pragma unroll 8
        for (int k = 0; k < 64; k++) {
            ulonglong2 w = *(const ulonglong2*)wp;
            ulonglong2 h = *(const ulonglong2*)hp;
            fma2(a00, w.x, h.x); fma2(a01, w.x, h.y);
            fma2(a10, w.y, h.x); fma2(a11, w.y, h.y);
            wp += 32; hp += 16;
        }
        {
            float* gp0 = g_p + kq * 512 + (rp * 2) * 16 + b4 * 4;
            float2 u;
            u = unpack2(a00); gp0[0] = u.x; gp0[1] = u.y;
            u = unpack2(a01); gp0[2] = u.x; gp0[3] = u.y;
            float* gp1 = gp0 + 16;
            u = unpack2(a10); gp1[0] = u.x; gp1[1] = u.y;
            u = unpack2(a11); gp1[2] = u.x; gp1[3] = u.y;
        }
        __syncthreads();

        // gates + state update; thread (unit cu, local batch cbl), tid<128
        float h = 0.f;
        if (gthr && act) {
            float gi = pi, gf = pf, gg = pg, go = po;
#pragma unroll
            for (int q = 0; q < 4; q++) {
                gi += g_p[q * 512 + (cu)      * 16 + cbl];
                gf += g_p[q * 512 + (8 + cu)  * 16 + cbl];
                gg += g_p[q * 512 + (16 + cu) * 16 + cbl];
                go += g_p[q * 512 + (24 + cu) * 16 + cbl];
            }
            gi = sig_fast(gi);
            gf = sig_fast(gf);
            go = sig_fast(go);
            gg = tanh_fast(gg);
            creg = gf * creg + gi * gg;
            h = go * tanh_fast(creg);
            __stcg(&g_hstate[layer][(s & 1) ^ 1][dir][hsoff + (ug0 + cu) * 16 + cbl], h);
        }
        if (gthr) __stcg(hpo + (size_t)s * H_ * 32, h);

        // publish arrival for the quarter we produce
        __syncthreads();
        if (tid == 0) red_rel(arrive_cnt);
    }
}

// ------------------- pooling + heads -------------------
__global__ void k_pool(const float* __restrict__ hout, const int* __restrict__ len,
                       float* __restrict__ pooled) {
    int b = blockIdx.x;
    int c = blockIdx.y * 128 + threadIdx.x;
    float s = 0.f;
    const float* p = hout + (size_t)b * T_ * D_ + c;
    for (int t = 0; t < T_; t++) s += p[(size_t)t * D_];
    int L = len[b];
    pooled[b * D_ + c] = s / (float)(L > 1 ? L : 1);
}

__global__ void k_utt(const float* __restrict__ pooled, const float* __restrict__ w1t,
                      const float* __restrict__ b1, const float* __restrict__ w2,
                      const float* __restrict__ b2, float* __restrict__ out) {
    int b = blockIdx.x, d = threadIdx.x;
    __shared__ float ps[D_];
    __shared__ float red[D_];
    ps[d] = pooled[b * D_ + d];
    __syncthreads();
    float acc = b1[d];
    for (int k = 0; k < D_; k++) acc = fmaf(ps[k], w1t[k * D_ + d], acc);
    red[d] = fmaxf(acc, 0.f) * w2[d];
    __syncthreads();
    for (int st = 256; st > 0; st >>= 1) {
        if (d < st) red[d] += red[d + st];
        __syncthreads();
    }
    if (d == 0) out[b] = red[0] + b2[0];
}

__global__ void k_seg(const float* __restrict__ hout, const int* __restrict__ segs,
                      const int* __restrict__ len, const int* __restrict__ seglen,
                      const float* __restrict__ w1t, const float* __restrict__ b1,
                      const float* __restrict__ w2, const float* __restrict__ b2,
                      float* __restrict__ out) {
    int si = blockIdx.x, b = blockIdx.y, d = threadIdx.x;
    __shared__ float mean_s[D_];
    __shared__ float red[D_];
    int L = len[b];
    int s0 = segs[(b * S_ + si) * 2 + 0];
    int e0 = segs[(b * S_ + si) * 2 + 1];
    int s = min(max(s0, 0), L);
    int e = max(s + 1, min(e0, L));
    float cnt = (float)(e - s);
    int ec = min(e, T_);
    float acc = 0.f;
    const float* p = hout + ((size_t)b * T_ + s) * D_ + d;
    for (int t = s; t < ec; t++, p += D_) acc += *p;
    mean_s[d] = acc / cnt;
    __syncthreads();
    float hv = b1[d];
    for (int k = 0; k < D_; k++) hv = fmaf(mean_s[k], w1t[k * D_ + d], hv);
    red[d] = fmaxf(hv, 0.f) * w2[d];
    __syncthreads();
    for (int st = 256; st > 0; st >>= 1) {
        if (d < st) red[d] += red[d + st];
        __syncthreads();
    }
    if (d == 0) {
        float sc = red[0] + b2[0];
        out[B_ + b * S_ + si] = (si < seglen[b]) ? sc : 0.f;
    }
}

// ------------------- driver -------------------
extern "C" void kernel_launch(void* const* d_in, const int* in_sizes, int n_in,
                              void* d_out, int out_size) {
    const float* features = (const float*)d_in[0];
    const int*   feat_len = (const int*)d_in[1];
    const int*   segs     = (const int*)d_in[2];
    const int*   seg_len  = (const int*)d_in[3];
    const float* conv1_w  = (const float*)d_in[4];
    const float* conv1_b  = (const float*)d_in[5];
    const float* conv2_w  = (const float*)d_in[6];
    const float* conv2_b  = (const float*)d_in[7];
    const float* wih0     = (const float*)d_in[8];
    const float* whh0     = (const float*)d_in[9];
    const float* bias0    = (const float*)d_in[10];
    const float* wih1     = (const float*)d_in[11];
    const float* whh1     = (const float*)d_in[12];
    const float* bias1    = (const float*)d_in[13];
    const float* seg_w1   = (const float*)d_in[14];
    const float* seg_b1   = (const float*)d_in[15];
    const float* seg_w2   = (const float*)d_in[16];
    const float* seg_b2   = (const float*)d_in[17];
    const float* utt_w1   = (const float*)d_in[18];
    const float* utt_b1   = (const float*)d_in[19];
    const float* utt_w2   = (const float*)d_in[20];
    const float* utt_b2   = (const float*)d_in[21];
    float* out = (float*)d_out;

    cudaFuncSetAttribute(k_scan, cudaFuncAttributeMaxDynamicSharedMemorySize, SCAN_SMEM);
    cudaFuncSetAttribute(k_gemm<0>,   cudaFuncAttributeMaxDynamicSharedMemorySize, GEMM_SMEM);
    cudaFuncSetAttribute(k_gemm<80>,  cudaFuncAttributeMaxDynamicSharedMemorySize, GEMM_SMEM);
    cudaFuncSetAttribute(k_gemm<256>, cudaFuncAttributeMaxDynamicSharedMemorySize, GEMM_SMEM);

    float *x1, *x2, *gproj, *gp2, *houtp, *hout0, *hout1, *w1t, *w2t,
          *wih0t, *wih1t, *wseg1t, *wutt1t, *pooled;
    cudaGetSymbolAddress((void**)&x1,     g_x1);
    cudaGetSymbolAddress((void**)&x2,     g_x2);
    cudaGetSymbolAddress((void**)&gproj,  g_gproj);
    cudaGetSymbolAddress((void**)&gp2,    g_gp2);
    cudaGetSymbolAddress((void**)&houtp,  g_houtp);
    cudaGetSymbolAddress((void**)&hout0,  g_hout0);
    cudaGetSymbolAddress((void**)&hout1,  g_hout1);
    cudaGetSymbolAddress((void**)&w1t,    g_w1t);
    cudaGetSymbolAddress((void**)&w2t,    g_w2t);
    cudaGetSymbolAddress((void**)&wih0t,  g_wih0t);
    cudaGetSymbolAddress((void**)&wih1t,  g_wih1t);
    cudaGetSymbolAddress((void**)&wseg1t, g_wseg1t);
    cudaGetSymbolAddress((void**)&wutt1t, g_wutt1t);
    cudaGetSymbolAddress((void**)&pooled, g_pooled);

    // 1: fused prep
    k_prep<<<2048, 256>>>(conv1_w, conv2_w, wih0, wih1, seg_w1, utt_w1);
    // 2: conv1 (im2col fused, K=240, padded weights; pipelined)
    k_gemm<80><<<dim3(256/GBN, M_/GBM), 256, GEMM_SMEM>>>(features, w1t, conv1_b, x1, M_, 256, 240, 1);
    // 3: conv2 (im2col fused; pipelined)
    k_gemm<256><<<dim3(256/GBN, M_/GBM), 256, GEMM_SMEM>>>(x1, w2t, conv2_b, x2, M_, 256, 768, 1);
    // 4: layer-0 input projection
    k_gemm<0><<<dim3(N2_/GBN, M_/GBM), 256, GEMM_SMEM>>>(x2, wih0t, bias0, gproj, M_, N2_, 256, 0);
    // 5: permute gproj (reversal folded in)
    k_permute<<<dim3(T_, 16, 2), 256>>>(gproj, gp2, feat_len);
    // 6: layer-0 scan
    k_scan<<<SCAN_NCTA, 256, SCAN_SMEM>>>(gp2, whh0, feat_len, houtp, 0);
    // 7: unpermute layer-0 output
    k_unpermute<<<dim3(T_, 4, 2), 256>>>(houtp, hout0, feat_len);
    // 8: layer-1 input projection
    k_gemm<0><<<dim3(N2_/GBN, M_/GBM), 256, GEMM_SMEM>>>(hout0, wih1t, bias1, gproj, M_, N2_, 512, 0);
    // 9: permute
    k_permute<<<dim3(T_, 16, 2), 256>>>(gproj, gp2, feat_len);
    // 10: layer-1 scan
    k_scan<<<SCAN_NCTA, 256, SCAN_SMEM>>>(gp2, whh1, feat_len, houtp, 1);
    // 11: unpermute layer-1 output
    k_unpermute<<<dim3(T_, 4, 2), 256>>>(houtp, hout1, feat_len);

    // pooling + heads
    k_pool<<<dim3(B_, 4), 128>>>(hout1, feat_len, pooled);
    k_utt<<<B_, D_>>>(pooled, wutt1t, utt_b1, utt_w2, utt_b2, out);
    k_seg<<<dim3(S_, B_), D_>>>(hout1, segs, feat_len, seg_len,
                                wseg1t, seg_b1, seg_w2, seg_b2, out);
}

// round 16
// speedup vs baseline: 1.2232x; 1.1524x over previous
#include <cuda_runtime.h>
#include <cuda_bf16.h>
#include <cstdint>

#define B_    32
#define T_    2000
#define F_    80
#define H_    256
#define S_    100
#define D_    512        // 2*H
#define M_    (B_*T_)    // 64000
#define N2_   2048       // 2 dirs * 4H

typedef unsigned long long ull;

// ------------------- packed f32x2 helpers (FFMA2) -------------------
__device__ __forceinline__ ull pack2(float x, float y) {
    ull r; asm("mov.b64 %0, {%1, %2};" : "=l"(r) : "f"(x), "f"(y)); return r;
}
__device__ __forceinline__ float2 unpack2(ull v) {
    float2 r; asm("mov.b64 {%0, %1}, %2;" : "=f"(r.x), "=f"(r.y) : "l"(v)); return r;
}
__device__ __forceinline__ void fma2(ull& d, ull a, ull b) {
    asm("fma.rn.f32x2 %0, %1, %2, %0;" : "+l"(d) : "l"(a), "l"(b));
}
__device__ __forceinline__ float rcpa(float x) {
    float r; asm("rcp.approx.f32 %0, %1;" : "=f"(r) : "f"(x)); return r;
}
__device__ __forceinline__ float sig_fast(float x) {
    return rcpa(1.f + __expf(-x));
}
__device__ __forceinline__ float tanh_fast(float x) {
    float e = __expf(2.f * x);
    return 1.f - 2.f * rcpa(e + 1.f);
}
__device__ __forceinline__ unsigned ld_acq(const unsigned* p) {
    unsigned v;
    asm volatile("ld.acquire.gpu.global.u32 %0, [%1];" : "=r"(v) : "l"(p) : "memory");
    return v;
}
__device__ __forceinline__ void red_rel(unsigned* p) {
    asm volatile("red.release.gpu.global.add.u32 [%0], 1;" :: "l"(p) : "memory");
}
__device__ __forceinline__ void cp16(uint32_t dst, const void* src) {
    asm volatile("cp.async.cg.shared.global [%0], [%1], 16;" :: "r"(dst), "l"(src));
}

// ------------------- scratch (static __device__, no allocs) -------------------
__device__ float g_x1 [(size_t)M_*256];          // conv1 out
__device__ float g_x2 [(size_t)M_*256];          // conv2 out
__device__ float g_gproj[(size_t)M_*N2_];        // input projections (reused L0/L1)
__device__ float g_gp2  [(size_t)2*T_*1024*B_];  // permuted [dir][s][n][b]
__device__ float g_houtp[(size_t)2*T_*H_*B_];    // scan out [dir][s][u][b]
__device__ float g_hout0[(size_t)M_*D_];         // layer0 bilstm out [b][t][d]
__device__ float g_hout1[(size_t)M_*D_];         // layer1 bilstm out
__device__ float g_w1t [256*256];                // padded K 240->256 (zero rows)
__device__ float g_w2t [768*256];
__device__ float g_wih0t[(size_t)256*N2_];
__device__ float g_wih1t[(size_t)512*N2_];
__device__ float g_wseg1t[D_*D_];
__device__ float g_wutt1t[D_*D_];
__device__ float g_pooled[B_*D_];
// [layer][buf][dir][bg*2048 + u*8 + cbl]
__device__ float g_hstate[2][2][2][H_*B_];
__device__ unsigned g_cnt[2][2][1024];           // [layer][dir][(bg*4+quarter)*64]

// ------------------- fused prep: all transposes + state zeroing -------------
__global__ void k_prep(const float* __restrict__ c1w, const float* __restrict__ c2w,
                       const float* __restrict__ wih0, const float* __restrict__ wih1,
                       const float* __restrict__ segw1, const float* __restrict__ uttw1)
{
    int stride = gridDim.x * blockDim.x;
    int tid = blockIdx.x * blockDim.x + threadIdx.x;

    // conv1 w: [Co][Ci][3] -> [3*Ci][Co], rows 240..255 zero (K padded to 256)
    for (int i = tid; i < 256 * 256; i += stride) {
        int row = i >> 8, co = i & 255;
        float v = 0.f;
        if (row < 240) {
            int k = row / 80, ci = row % 80;
            v = c1w[co * 240 + ci * 3 + k];
        }
        g_w1t[row * 256 + co] = v;
    }
    for (int i = tid; i < 256 * 256 * 3; i += stride) {      // conv2 w
        int k = i % 3, ci = (i / 3) % 256, co = i / 768;
        g_w2t[(k * 256 + ci) * 256 + co] = c2w[i];
    }
    for (int i = tid; i < 2048 * 256; i += stride) {
        int k = i % 256, dr = i / 256;
        g_wih0t[(size_t)k * 2048 + dr] = wih0[i];
    }
    for (int i = tid; i < 2048 * 512; i += stride) {
        int k = i % 512, dr = i / 512;
        g_wih1t[(size_t)k * 2048 + dr] = wih1[i];
    }
    for (int i = tid; i < D_ * D_; i += stride) {
        int d = i / D_, k = i % D_;
        g_wseg1t[k * D_ + d] = segw1[i];
        g_wutt1t[k * D_ + d] = uttw1[i];
    }
    {
        float* p = &g_hstate[0][0][0][0];
        for (int i = tid; i < 2 * 2 * 2 * H_ * B_; i += stride) p[i] = 0.f;
        unsigned* c = &g_cnt[0][0][0];
        for (int i = tid; i < 2 * 2 * 1024; i += stride) c[i] = 0u;
    }
}

// ---- permute gproj -> gp2[dir][s][n][b], reversal folded in ----
__global__ void __launch_bounds__(256)
k_permute(const float* __restrict__ gproj, float* __restrict__ gp2,
          const int* __restrict__ len)
{
    __shared__ float tile[32][65];
    __shared__ int Ls[32];
    int s = blockIdx.x, nc = blockIdx.y, dir = blockIdx.z;
    int tid = threadIdx.x;
    if (tid < 32) Ls[tid] = len[tid];
    __syncthreads();

    int b  = tid >> 3;
    int ng = (tid & 7) * 8;
    int L  = Ls[b];
    int t  = dir ? (L - 1 - s) : s;
    bool ok = (s < L);
    int n0 = nc * 64;
    const float* src = gproj + ((size_t)b * T_ + (ok ? t : 0)) * N2_ + dir * 1024 + n0 + ng;
    float4 v0 = make_float4(0.f, 0.f, 0.f, 0.f), v1 = v0;
    if (ok) { v0 = *(const float4*)src; v1 = *(const float4*)(src + 4); }
    tile[b][ng + 0] = v0.x; tile[b][ng + 1] = v0.y;
    tile[b][ng + 2] = v0.z; tile[b][ng + 3] = v0.w;
    tile[b][ng + 4] = v1.x; tile[b][ng + 5] = v1.y;
    tile[b][ng + 6] = v1.z; tile[b][ng + 7] = v1.w;
    __syncthreads();

    float* dst = gp2 + (((size_t)dir * T_ + s) * 1024 + n0) * 32;
    int bb = tid & 31;
#pragma unroll
    for (int i = 0; i < 8; i++) {
        int nl = (tid >> 5) + i * 8;
        dst[(size_t)nl * 32 + bb] = tile[bb][nl];
    }
}

// ---- unpermute houtp[dir][s][u][b] -> hout[b][t][dir*H+u] ----
// Guards s >= L[b] with zeros (scan stops at per-domain maxL; tail is stale).
__global__ void __launch_bounds__(256)
k_unpermute(const float* __restrict__ houtp, float* __restrict__ hout,
            const int* __restrict__ len)
{
    __shared__ float tile[64][33];
    __shared__ int Ls[32];
    int s = blockIdx.x, uc = blockIdx.y, dir = blockIdx.z;
    int tid = threadIdx.x;
    if (tid < 32) Ls[tid] = len[tid];
    __syncthreads();

    const float* src = houtp + (((size_t)dir * T_ + s) * H_ + uc * 64) * 32;
    int ur = tid >> 5, b = tid & 31;
#pragma unroll
    for (int j = 0; j < 8; j++) {
        int u = ur * 8 + j;
        tile[u][b] = src[(size_t)u * 32 + b];
    }
    __syncthreads();

    int b2 = tid >> 3, ug = tid & 7;
    int L = Ls[b2];
    bool act = (s < L);
    int t = act ? (dir ? (L - 1 - s) : s) : s;
    float v[8];
#pragma unroll
    for (int j = 0; j < 8; j++) v[j] = act ? tile[ug * 8 + j][b2] : 0.f;
    float* dst = hout + ((size_t)b2 * T_ + t) * D_ + dir * H_ + uc * 64 + ug * 8;
    *(float4*)dst       = make_float4(v[0], v[1], v[2], v[3]);
    *(float4*)(dst + 4) = make_float4(v[4], v[5], v[6], v[7]);
}

// ---- tiled SGEMM (f32x2), GBK=32; As double + Bs triple buffer,
//      single __syncthreads per tile; A from plain (CI=0) or im2col gather ----
#define GBM 128
#define GBN 128
#define GBK 32
#define GEMM_SMEM (5 * GBK * 132 * 4)    // As[2] + Bs[3]

template <int CI>
__global__ void __launch_bounds__(256, 2)
k_gemm(const float* __restrict__ A, const float* __restrict__ Bm,
       const float* __restrict__ bias, float* __restrict__ C,
       int M, int N, int K, int relu)
{
    extern __shared__ float gsm[];
    float (*As)[GBK][132] = (float(*)[GBK][132])gsm;
    float (*Bs)[GBK][132] = (float(*)[GBK][132])(gsm + 2 * GBK * 132);

    int bm = blockIdx.y * GBM;
    int bn = blockIdx.x * GBN;
    int tid = threadIdx.x;
    int tr = tid >> 4;
    int tc = tid & 15;

    ull acc[4][8];
#pragma unroll
    for (int i = 0; i < 4; i++)
#pragma unroll
        for (int j = 0; j < 8; j++) acc[i][j] = 0ull;

    int Kr = (K + GBK - 1) & ~(GBK - 1);
    int ntiles = Kr / GBK;
    float4 areg[4];

    auto loadA = [&](int k0) {
#pragma unroll
        for (int i = 0; i < 4; i++) {
            int idx = tid + i * 256;
            int row = idx >> 3, c4 = (idx & 7) * 4;
            if (CI == 0) {
                areg[i] = *(const float4*)&A[(size_t)(bm + row) * K + k0 + c4];
            } else {
                int r = bm + row;
                int b = r / T_, t = r % T_;
                int kk = k0 + c4;
                int kt = kk / CI, ci = kk - kt * CI;
                int tt = t + kt - 1;
                areg[i] = (kk < K && tt >= 0 && tt < T_)
                    ? *(const float4*)&A[((size_t)b * T_ + tt) * CI + ci]
                    : make_float4(0.f, 0.f, 0.f, 0.f);
            }
        }
    };

#pragma unroll
    for (int i = 0; i < 4; i++) {
        int idx = tid + i * 256;
        int kr = idx >> 5, n4 = (idx & 31) * 4;
        cp16((uint32_t)__cvta_generic_to_shared(&Bs[0][kr][n4]),
             &Bm[(size_t)kr * N + bn + n4]);
    }
    asm volatile("cp.async.commit_group;");
    loadA(0);

    int bufB = 0;
    for (int it = 0; it < ntiles; it++) {
        int bufA = it & 1;
#pragma unroll
        for (int i = 0; i < 4; i++) {
            int idx = tid + i * 256;
            int row = idx >> 3, c4 = (idx & 7) * 4;
            As[bufA][c4 + 0][row] = areg[i].x;
            As[bufA][c4 + 1][row] = areg[i].y;
            As[bufA][c4 + 2][row] = areg[i].z;
            As[bufA][c4 + 3][row] = areg[i].w;
        }
        if (it + 1 < ntiles) {
            int k1 = (it + 1) * GBK;
            int nb = bufB + 1; if (nb == 3) nb = 0;
#pragma unroll
            for (int i = 0; i < 4; i++) {
                int idx = tid + i * 256;
                int kr = idx >> 5, n4 = (idx & 31) * 4;
                cp16((uint32_t)__cvta_generic_to_shared(&Bs[nb][kr][n4]),
                     &Bm[(size_t)(k1 + kr) * N + bn + n4]);
            }
            asm volatile("cp.async.commit_group;");
            loadA(k1);
            asm volatile("cp.async.wait_group 1;");
        } else {
            asm volatile("cp.async.wait_group 0;");
        }
        __syncthreads();           // single barrier per tile
#pragma unroll 16
        for (int k = 0; k < GBK; k++) {
            ulonglong2 a0 = *(const ulonglong2*)&As[bufA][k][tr * 8];
            ulonglong2 a1 = *(const ulonglong2*)&As[bufA][k][tr * 8 + 4];
            float4 b0 = *(const float4*)&Bs[bufB][k][tc * 4];
            float4 b1 = *(const float4*)&Bs[bufB][k][tc * 4 + 64];
            ull ar0 = a0.x, ar1 = a0.y, ar2 = a1.x, ar3 = a1.y;
            ull bd0 = pack2(b0.x, b0.x), bd1 = pack2(b0.y, b0.y);
            ull bd2 = pack2(b0.z, b0.z), bd3 = pack2(b0.w, b0.w);
            ull bd4 = pack2(b1.x, b1.x), bd5 = pack2(b1.y, b1.y);
            ull bd6 = pack2(b1.z, b1.z), bd7 = pack2(b1.w, b1.w);
            fma2(acc[0][0], ar0, bd0); fma2(acc[0][1], ar0, bd1);
            fma2(acc[0][2], ar0, bd2); fma2(acc[0][3], ar0, bd3);
            fma2(acc[0][4], ar0, bd4); fma2(acc[0][5], ar0, bd5);
            fma2(acc[0][6], ar0, bd6); fma2(acc[0][7], ar0, bd7);
            fma2(acc[1][0], ar1, bd0); fma2(acc[1][1], ar1, bd1);
            fma2(acc[1][2], ar1, bd2); fma2(acc[1][3], ar1, bd3);
            fma2(acc[1][4], ar1, bd4); fma2(acc[1][5], ar1, bd5);
            fma2(acc[1][6], ar1, bd6); fma2(acc[1][7], ar1, bd7);
            fma2(acc[2][0], ar2, bd0); fma2(acc[2][1], ar2, bd1);
            fma2(acc[2][2], ar2, bd2); fma2(acc[2][3], ar2, bd3);
            fma2(acc[2][4], ar2, bd4); fma2(acc[2][5], ar2, bd5);
            fma2(acc[2][6], ar2, bd6); fma2(acc[2][7], ar2, bd7);
            fma2(acc[3][0], ar3, bd0); fma2(acc[3][1], ar3, bd1);
            fma2(acc[3][2], ar3, bd2); fma2(acc[3][3], ar3, bd3);
            fma2(acc[3][4], ar3, bd4); fma2(acc[3][5], ar3, bd5);
            fma2(acc[3][6], ar3, bd6); fma2(acc[3][7], ar3, bd7);
        }
        bufB = bufB + 1; if (bufB == 3) bufB = 0;
    }

    float bb[8];
    if (bias) {
        float4 bv0 = *(const float4*)&bias[bn + tc * 4];
        float4 bv1 = *(const float4*)&bias[bn + tc * 4 + 64];
        bb[0] = bv0.x; bb[1] = bv0.y; bb[2] = bv0.z; bb[3] = bv0.w;
        bb[4] = bv1.x; bb[5] = bv1.y; bb[6] = bv1.z; bb[7] = bv1.w;
    } else {
#pragma unroll
        for (int c = 0; c < 8; c++) bb[c] = 0.f;
    }
#pragma unroll
    for (int rp = 0; rp < 4; rp++) {
        float o0[8], o1[8];
#pragma unroll
        for (int c = 0; c < 8; c++) {
            float2 u = unpack2(acc[rp][c]);
            o0[c] = u.x + bb[c];
            o1[c] = u.y + bb[c];
            if (relu) { o0[c] = fmaxf(o0[c], 0.f); o1[c] = fmaxf(o1[c], 0.f); }
        }
        int row0 = bm + tr * 8 + rp * 2;
        float* p0 = &C[(size_t)row0 * N + bn];
        float* p1 = p0 + N;
        *(float4*)(p0 + tc * 4)      = make_float4(o0[0], o0[1], o0[2], o0[3]);
        *(float4*)(p0 + tc * 4 + 64) = make_float4(o0[4], o0[5], o0[6], o0[7]);
        *(float4*)(p1 + tc * 4)      = make_float4(o1[0], o1[1], o1[2], o1[3]);
        *(float4*)(p1 + tc * 4 + 64) = make_float4(o1[4], o1[5], o1[6], o1[7]);
    }
}

// ------------------- persistent BiLSTM scan (one layer, both dirs) ----------
// BATCH-SPLIT x4: 128 CTAs = 2 dirs x 4 batch-groups(8) x 16 unit-chunks(16u).
// Each CTA: 16 units x 8 batches; 4 k-groups of 64 threads consume the 4
// h-quarters of their (dir,bg) domain (16 CTAs, 4 producers/counter).
#define SCAN_NCTA 128
#define SCAN_SMEM (147584)   // w2 128KB + h_s 8KB + g_p 8KB + L pad

__global__ void __launch_bounds__(256, 1)
k_scan(const float* __restrict__ gp2, const float* __restrict__ whh,
       const int* __restrict__ lengths, float* __restrict__ houtp, int layer)
{
    extern __shared__ float sm[];
    ull*   w2  = (ull*)sm;                 // [256 k][64 r] dup'd weights (128 KB)
    float* h_s = sm + 32768;               // [256 k][8 b] (8 KB)
    float* g_p = sm + 34816;               // [4][64 r][8 b] partials (8 KB)
    int*   L_s = (int*)(sm + 36864);       // [8]

    const int bid = blockIdx.x;
    const int dir = bid >> 6;
    const int wd  = bid & 63;
    const int bg  = wd >> 4;               // batch group 0..3
    const int cg  = wd & 15;               // unit chunk 0..15
    const int ug0 = cg * 16;               // first of 16 units
    const int tid = threadIdx.x;

    // weights: local row r = q*16+j (gate q, unit j) <-> whh row q*256+ug0+j
    for (int i = tid; i < 16384; i += 256) {
        int k = i >> 6, r = i & 63;
        int q = r >> 4, j = r & 15;
        float w = whh[(size_t)dir * 262144 + (size_t)(q * 256 + ug0 + j) * 256 + k];
        w2[(size_t)k * 64 + r] = pack2(w, w);
    }
    if (tid < 8) L_s[tid] = lengths[bg * 8 + tid];
    __syncthreads();

    int smax = 1;
#pragma unroll
    for (int i = 0; i < 8; i++) smax = max(smax, L_s[i]);

    const int kq = tid >> 6;             // k-quarter this group consumes
    const int lt = tid & 63;
    const int rp = lt >> 1;              // row pair 0..31 (rows 2rp, 2rp+1)
    const int b2q = lt & 1;              // local batch quad 0..1
    const int jown = cg >> 2;            // h-quarter this CTA produces
    const int cu  = (tid >> 3) & 15;     // unit 0..15 (gate phase, tid<128)
    const int cbl = tid & 7;             // local batch (gate phase, tid<128)
    const bool gthr = tid < 128;
    const bool poller = (lt == 0);
    const int Lcb = L_s[cbl];
    float creg = 0.f;

    unsigned* arrive_cnt = &g_cnt[layer][dir][(bg * 4 + jown) * 64];
    unsigned* poll_cnt   = &g_cnt[layer][dir][(bg * 4 + kq) * 64];

    const float* gbase = gp2 + ((size_t)dir * T_ * 1024 + ug0 + cu) * 32 + bg * 8 + cbl;
    float* hpo = houtp + ((size_t)dir * T_ * H_ + ug0 + cu) * 32 + bg * 8 + cbl;
    const int hsoff = bg * 2048;

    for (int s = 0; s < smax; s++) {
        bool act = s < Lcb;

        // prefetch gates for this step
        float pi = 0.f, pf = 0.f, pg = 0.f, po = 0.f;
        if (gthr) {
            const float* gp = gbase + (size_t)s * 1024 * 32;
            pi = __ldcg(gp);
            pf = __ldcg(gp + 256 * 32);
            pg = __ldcg(gp + 512 * 32);
            po = __ldcg(gp + 768 * 32);
        }

        // wait for the 4 producers of OUR quarter, then load it (2 KB)
        if (poller && s > 0) {
            unsigned tgt = (unsigned)s * 4u;
            while (ld_acq(poll_cnt) < tgt) { }
        }
        asm volatile("bar.sync %0, 64;" :: "r"(1 + kq) : "memory");
        {
            const float* hsrc = &g_hstate[layer][s & 1][dir][hsoff + kq * 512];
            float*       hdst = h_s + kq * 512;
#pragma unroll
            for (int i = 0; i < 2; i++) {
                int idx = (lt + i * 64) * 4;
                *(float4*)(hdst + idx) = __ldcg((const float4*)(hsrc + idx));
            }
        }
        asm volatile("bar.sync %0, 64;" :: "r"(1 + kq) : "memory");

        // dot: rows (2rp,2rp+1) x local batches (4*b2q..+3) over k-quarter
        ull a00 = 0ull, a01 = 0ull, a10 = 0ull, a11 = 0ull;
        const ull*   wp = w2 + (size_t)(kq * 64) * 64 + rp * 2;
        const float* hp = h_s + (kq * 64) * 8 + b2q * 4;
#pragma unroll 8
        for (int k = 0; k < 64; k++) {
            ulonglong2 w = *(const ulonglong2*)wp;
            ulonglong2 h = *(const ulonglong2*)hp;
            fma2(a00, w.x, h.x); fma2(a01, w.x, h.y);
            fma2(a10, w.y, h.x); fma2(a11, w.y, h.y);
            wp += 64; hp += 8;
        }
        {
            float* gp0 = g_p + kq * 512 + (rp * 2) * 8 + b2q * 4;
            float2 u;
            u = unpack2(a00); gp0[0] = u.x; gp0[1] = u.y;
            u = unpack2(a01); gp0[2] = u.x; gp0[3] = u.y;
            float* gp1 = gp0 + 8;
            u = unpack2(a10); gp1[0] = u.x; gp1[1] = u.y;
            u = unpack2(a11); gp1[2] = u.x; gp1[3] = u.y;
        }
        __syncthreads();

        // gates + state update; thread (unit cu, local batch cbl), tid<128
        float h = 0.f;
        if (gthr && act) {
            float gi = pi, gf = pf, gg = pg, go = po;
#pragma unroll
            for (int q = 0; q < 4; q++) {
                gi += g_p[q * 512 + (cu)       * 8 + cbl];
                gf += g_p[q * 512 + (16 + cu)  * 8 + cbl];
                gg += g_p[q * 512 + (32 + cu)  * 8 + cbl];
                go += g_p[q * 512 + (48 + cu)  * 8 + cbl];
            }
            gi = sig_fast(gi);
            gf = sig_fast(gf);
            go = sig_fast(go);
            gg = tanh_fast(gg);
            creg = gf * creg + gi * gg;
            h = go * tanh_fast(creg);
            __stcg(&g_hstate[layer][(s & 1) ^ 1][dir][hsoff + (ug0 + cu) * 8 + cbl], h);
        }
        if (gthr) __stcg(hpo + (size_t)s * H_ * 32, h);

        // publish arrival for the quarter we produce
        __syncthreads();
        if (tid == 0) red_rel(arrive_cnt);
    }
}

// ------------------- pooling + heads -------------------
__global__ void k_pool(const float* __restrict__ hout, const int* __restrict__ len,
                       float* __restrict__ pooled) {
    int b = blockIdx.x;
    int c = blockIdx.y * 128 + threadIdx.x;
    float s = 0.f;
    const float* p = hout + (size_t)b * T_ * D_ + c;
    for (int t = 0; t < T_; t++) s += p[(size_t)t * D_];
    int L = len[b];
    pooled[b * D_ + c] = s / (float)(L > 1 ? L : 1);
}

__global__ void k_utt(const float* __restrict__ pooled, const float* __restrict__ w1t,
                      const float* __restrict__ b1, const float* __restrict__ w2,
                      const float* __restrict__ b2, float* __restrict__ out) {
    int b = blockIdx.x, d = threadIdx.x;
    __shared__ float ps[D_];
    __shared__ float red[D_];
    ps[d] = pooled[b * D_ + d];
    __syncthreads();
    float acc = b1[d];
    for (int k = 0; k < D_; k++) acc = fmaf(ps[k], w1t[k * D_ + d], acc);
    red[d] = fmaxf(acc, 0.f) * w2[d];
    __syncthreads();
    for (int st = 256; st > 0; st >>= 1) {
        if (d < st) red[d] += red[d + st];
        __syncthreads();
    }
    if (d == 0) out[b] = red[0] + b2[0];
}

__global__ void k_seg(const float* __restrict__ hout, const int* __restrict__ segs,
                      const int* __restrict__ len, const int* __restrict__ seglen,
                      const float* __restrict__ w1t, const float* __restrict__ b1,
                      const float* __restrict__ w2, const float* __restrict__ b2,
                      float* __restrict__ out) {
    int si = blockIdx.x, b = blockIdx.y, d = threadIdx.x;
    __shared__ float mean_s[D_];
    __shared__ float red[D_];
    int L = len[b];
    int s0 = segs[(b * S_ + si) * 2 + 0];
    int e0 = segs[(b * S_ + si) * 2 + 1];
    int s = min(max(s0, 0), L);
    int e = max(s + 1, min(e0, L));
    float cnt = (float)(e - s);
    int ec = min(e, T_);
    float acc = 0.f;
    const float* p = hout + ((size_t)b * T_ + s) * D_ + d;
    for (int t = s; t < ec; t++, p += D_) acc += *p;
    mean_s[d] = acc / cnt;
    __syncthreads();
    float hv = b1[d];
    for (int k = 0; k < D_; k++) hv = fmaf(mean_s[k], w1t[k * D_ + d], hv);
    red[d] = fmaxf(hv, 0.f) * w2[d];
    __syncthreads();
    for (int st = 256; st > 0; st >>= 1) {
        if (d < st) red[d] += red[d + st];
        __syncthreads();
    }
    if (d == 0) {
        float sc = red[0] + b2[0];
        out[B_ + b * S_ + si] = (si < seglen[b]) ? sc : 0.f;
    }
}

// ------------------- driver -------------------
extern "C" void kernel_launch(void* const* d_in, const int* in_sizes, int n_in,
                              void* d_out, int out_size) {
    const float* features = (const float*)d_in[0];
    const int*   feat_len = (const int*)d_in[1];
    const int*   segs     = (const int*)d_in[2];
    const int*   seg_len  = (const int*)d_in[3];
    const float* conv1_w  = (const float*)d_in[4];
    const float* conv1_b  = (const float*)d_in[5];
    const float* conv2_w  = (const float*)d_in[6];
    const float* conv2_b  = (const float*)d_in[7];
    const float* wih0     = (const float*)d_in[8];
    const float* whh0     = (const float*)d_in[9];
    const float* bias0    = (const float*)d_in[10];
    const float* wih1     = (const float*)d_in[11];
    const float* whh1     = (const float*)d_in[12];
    const float* bias1    = (const float*)d_in[13];
    const float* seg_w1   = (const float*)d_in[14];
    const float* seg_b1   = (const float*)d_in[15];
    const float* seg_w2   = (const float*)d_in[16];
    const float* seg_b2   = (const float*)d_in[17];
    const float* utt_w1   = (const float*)d_in[18];
    const float* utt_b1   = (const float*)d_in[19];
    const float* utt_w2   = (const float*)d_in[20];
    const float* utt_b2   = (const float*)d_in[21];
    float* out = (float*)d_out;

    cudaFuncSetAttribute(k_scan, cudaFuncAttributeMaxDynamicSharedMemorySize, SCAN_SMEM);
    cudaFuncSetAttribute(k_gemm<0>,   cudaFuncAttributeMaxDynamicSharedMemorySize, GEMM_SMEM);
    cudaFuncSetAttribute(k_gemm<80>,  cudaFuncAttributeMaxDynamicSharedMemorySize, GEMM_SMEM);
    cudaFuncSetAttribute(k_gemm<256>, cudaFuncAttributeMaxDynamicSharedMemorySize, GEMM_SMEM);

    float *x1, *x2, *gproj, *gp2, *houtp, *hout0, *hout1, *w1t, *w2t,
          *wih0t, *wih1t, *wseg1t, *wutt1t, *pooled;
    cudaGetSymbolAddress((void**)&x1,     g_x1);
    cudaGetSymbolAddress((void**)&x2,     g_x2);
    cudaGetSymbolAddress((void**)&gproj,  g_gproj);
    cudaGetSymbolAddress((void**)&gp2,    g_gp2);
    cudaGetSymbolAddress((void**)&houtp,  g_houtp);
    cudaGetSymbolAddress((void**)&hout0,  g_hout0);
    cudaGetSymbolAddress((void**)&hout1,  g_hout1);
    cudaGetSymbolAddress((void**)&w1t,    g_w1t);
    cudaGetSymbolAddress((void**)&w2t,    g_w2t);
    cudaGetSymbolAddress((void**)&wih0t,  g_wih0t);
    cudaGetSymbolAddress((void**)&wih1t,  g_wih1t);
    cudaGetSymbolAddress((void**)&wseg1t, g_wseg1t);
    cudaGetSymbolAddress((void**)&wutt1t, g_wutt1t);
    cudaGetSymbolAddress((void**)&pooled, g_pooled);

    // 1: fused prep
    k_prep<<<2048, 256>>>(conv1_w, conv2_w, wih0, wih1, seg_w1, utt_w1);
    // 2: conv1 (im2col fused, K=240, padded weights; pipelined)
    k_gemm<80><<<dim3(256/GBN, M_/GBM), 256, GEMM_SMEM>>>(features, w1t, conv1_b, x1, M_, 256, 240, 1);
    // 3: conv2 (im2col fused; pipelined)
    k_gemm<256><<<dim3(256/GBN, M_/GBM), 256, GEMM_SMEM>>>(x1, w2t, conv2_b, x2, M_, 256, 768, 1);
    // 4: layer-0 input projection
    k_gemm<0><<<dim3(N2_/GBN, M_/GBM), 256, GEMM_SMEM>>>(x2, wih0t, bias0, gproj, M_, N2_, 256, 0);
    // 5: permute gproj (reversal folded in)
    k_permute<<<dim3(T_, 16, 2), 256>>>(gproj, gp2, feat_len);
    // 6: layer-0 scan
    k_scan<<<SCAN_NCTA, 256, SCAN_SMEM>>>(gp2, whh0, feat_len, houtp, 0);
    // 7: unpermute layer-0 output
    k_unpermute<<<dim3(T_, 4, 2), 256>>>(houtp, hout0, feat_len);
    // 8: layer-1 input projection
    k_gemm<0><<<dim3(N2_/GBN, M_/GBM), 256, GEMM_SMEM>>>(hout0, wih1t, bias1, gproj, M_, N2_, 512, 0);
    // 9: permute
    k_permute<<<dim3(T_, 16, 2), 256>>>(gproj, gp2, feat_len);
    // 10: layer-1 scan
    k_scan<<<SCAN_NCTA, 256, SCAN_SMEM>>>(gp2, whh1, feat_len, houtp, 1);
    // 11: unpermute layer-1 output
    k_unpermute<<<dim3(T_, 4, 2), 256>>>(houtp, hout1, feat_len);

    // pooling + heads
    k_pool<<<dim3(B_, 4), 128>>>(hout1, feat_len, pooled);
    k_utt<<<B_, D_>>>(pooled, wutt1t, utt_b1, utt_w2, utt_b2, out);
    k_seg<<<dim3(S_, B_), D_>>>(hout1, segs, feat_len, seg_len,
                                wseg1t, seg_b1, seg_w2, seg_b2, out);
}